// round 13
// baseline (speedup 1.0000x reference)
#include <cuda_runtime.h>
#include <cuda_fp16.h>
#include <cstdint>

// Problem constants
#define Bn 2
#define Sn 2048
#define Dn 1024
#define Hn 16
#define HD 64
#define Mt (Bn * Sn)        // 4096
#define MK (Mt * Dn)        // 4194304
#define NK (Dn * Dn)        // 1048576

typedef __half hf;

// ---------------- scratch (__device__ globals; no allocs) ----------------
__device__ hf gx[3][MK];                  // fp16 inputs q,k,v  [m][k]
__device__ hf gw[3][NK];                  // Wq/Wk/Wv as Bt [n][k], fp16
__device__ hf gwo[NK];                    // Wo as Bt [n][k], fp16
__device__ hf gQ[MK];                     // Q proj (scaled by 0.125*log2e)
__device__ hf gK[MK];                     // K proj, fp16 [bh*Sn+s][64]
__device__ hf gVt[MK];                    // V proj transposed, fp16 [bh*64+e][Sn]
__device__ hf gC[MK];                     // attention out (cat) fp16 [m][1024]

// ---------------- helpers ----------------
__device__ __forceinline__ uint32_t smem_u32(const void* p) {
    uint32_t a;
    asm("{ .reg .u64 t; cvta.to.shared.u64 t, %1; cvt.u32.u64 %0, t; }"
        : "=r"(a) : "l"(p));
    return a;
}
__device__ __forceinline__ uint32_t pack_f16(float x, float y) {
    uint32_t r;
    asm("cvt.rn.f16x2.f32 %0, %1, %2;" : "=r"(r) : "f"(y), "f"(x));
    return r;   // low half = x, high half = y
}
__device__ __forceinline__ uint32_t ex2_h2(uint32_t x) {
    uint32_t r;
    asm("ex2.approx.f16x2 %0, %1;" : "=r"(r) : "r"(x));
    return r;
}
__device__ __forceinline__ void mma_f16(float* c, const uint32_t* a, const uint32_t* b) {
    asm volatile(
        "mma.sync.aligned.m16n8k16.row.col.f32.f16.f16.f32 "
        "{%0,%1,%2,%3}, {%4,%5,%6,%7}, {%8,%9}, {%0,%1,%2,%3};"
        : "+f"(c[0]), "+f"(c[1]), "+f"(c[2]), "+f"(c[3])
        : "r"(a[0]), "r"(a[1]), "r"(a[2]), "r"(a[3]), "r"(b[0]), "r"(b[1]));
}
__device__ __forceinline__ void ldmx4(uint32_t* r, uint32_t a) {
    asm volatile("ldmatrix.sync.aligned.m8n8.x4.shared.b16 {%0,%1,%2,%3}, [%4];"
        : "=r"(r[0]), "=r"(r[1]), "=r"(r[2]), "=r"(r[3]) : "r"(a));
}
// sum 8 packed f16x2 pairs (columns a and b of ph[4][4]) -> fp32
__device__ __forceinline__ float psum(const uint32_t ph[4][4], int a, int b) {
    __half2 s = __hadd2(*(const __half2*)&ph[0][a], *(const __half2*)&ph[0][b]);
    s = __hadd2(s, __hadd2(*(const __half2*)&ph[1][a], *(const __half2*)&ph[1][b]));
    s = __hadd2(s, __hadd2(*(const __half2*)&ph[2][a], *(const __half2*)&ph[2][b]));
    s = __hadd2(s, __hadd2(*(const __half2*)&ph[3][a], *(const __half2*)&ph[3][b]));
    const float2 f = __half22float2(s);
    return f.x + f.y;
}
#define CP16(dst_u32, src_gptr) \
    asm volatile("cp.async.cg.shared.global [%0], [%1], 16;" \
        :: "r"(dst_u32), "l"(src_gptr))
#define CP_COMMIT() asm volatile("cp.async.commit_group;" ::: "memory")
#define CP_WAIT(n)  asm volatile("cp.async.wait_group %0;" :: "n"(n) : "memory")

// ===========================================================================
// Conversion kernels (run once per launch; memory-bound)
// ===========================================================================
__global__ __launch_bounds__(256)
void conv_in(const float* __restrict__ q, const float* __restrict__ k,
             const float* __restrict__ v)
{
    const int z = blockIdx.z;
    const float* src = (z == 0) ? q : (z == 1) ? k : v;
    hf* d = gx[z];
    const size_t i = ((size_t)blockIdx.x * 256 + threadIdx.x) * 8;
    const float4 a  = *(const float4*)(src + i);
    const float4 b2 = *(const float4*)(src + i + 4);
    uint32_t h[4];
    h[0] = pack_f16(a.x,  a.y);
    h[1] = pack_f16(a.z,  a.w);
    h[2] = pack_f16(b2.x, b2.y);
    h[3] = pack_f16(b2.z, b2.w);
    *(uint4*)(d + i) = *(uint4*)h;
}

__global__ __launch_bounds__(256)
void conv_w(const float* __restrict__ Wq, const float* __restrict__ Wk,
            const float* __restrict__ Wv, const float* __restrict__ Wo)
{
    const int z = blockIdx.z;
    const int idx = blockIdx.x * 256 + threadIdx.x;   // 262144 per z
    if (z < 3) {
        const float* W = (z == 0) ? Wq : (z == 1) ? Wk : Wv;   // [H][K][64]
        const int e4 = (idx & 15) * 4;
        const int hk = idx >> 4;
        const int h = hk >> 10, k = hk & 1023;
        const float4 w = *(const float4*)(W + ((size_t)h * Dn + k) * HD + e4);
        const float wv[4] = {w.x, w.y, w.z, w.w};
#pragma unroll
        for (int j = 0; j < 4; j++)
            gw[z][(size_t)(h * HD + e4 + j) * Dn + k] = __float2half_rn(wv[j]);
    } else {                                           // Wo [K=1024][N=1024]
        const int n4 = (idx & 255) * 4;
        const int k  = idx >> 8;
        const float4 w = *(const float4*)(Wo + (size_t)k * Dn + n4);
        const float wv[4] = {w.x, w.y, w.z, w.w};
#pragma unroll
        for (int j = 0; j < 4; j++)
            gwo[(size_t)(n4 + j) * Dn + k] = __float2half_rn(wv[j]);
    }
}

// ===========================================================================
// GEMM mainloop: 256x128 CTA tile, 512 threads = 16 warps (4m x 4n),
// warp tile 64x32, K-step 64 (two 32-k swizzled subtiles per stage).
// Pure fp16, 1 MMA per fragment pair. 3-stage cp.async ring, ONE
// __syncthreads per K-tile (16 iters). 4 warps/SMSP for latency hiding.
// Stage: A @0 (32KB: sub0 @0, sub1 @16384), B @32768 (16KB: sub0/sub1 8KB).
// ===========================================================================
#define GSTAGE 49152
#define GEMM_SMEM (3 * GSTAGE)

__device__ __forceinline__ void gemm_stage(uint32_t smb, int buf,
    const hf* Ag, const hf* Bg, int bm, int bn, int kt, int tid)
{
    const uint32_t b0 = smb + buf * GSTAGE;
#pragma unroll
    for (int i = 0; i < 6; i++) {
        const int idx = i * 512 + tid;   // 0..3071
        if (idx < 2048) {                // A: 256 rows x 8 chunks
            const int row = idx >> 3;
            const int ch  = idx & 7;
            const int sub = ch >> 2;
            const int chs = (ch & 3) ^ ((row >> 1) & 3);
            CP16(b0 + sub * 16384 + row * 64 + chs * 16,
                 Ag + (size_t)(bm + row) * Dn + kt + ch * 8);
        } else {                         // B: 128 rows x 8 chunks
            const int c2 = idx - 2048;
            const int row = c2 >> 3;
            const int ch  = c2 & 7;
            const int sub = ch >> 2;
            const int chs = (ch & 3) ^ ((row >> 1) & 3);
            CP16(b0 + 32768 + sub * 8192 + row * 64 + chs * 16,
                 Bg + (size_t)(bn + row) * Dn + kt + ch * 8);
        }
    }
}

__device__ __forceinline__ void gemm_main(uint32_t smb,
    const hf* Ag, const hf* Bg, int bm, int bn, int tid, float c[4][4][4])
{
    const int lane = tid & 31;
    const int warp = tid >> 5;           // 0..15
    const int lrow = lane & 7;
    const int lmat = lane >> 3;
    const int wm = (warp >> 2) * 64;     // 0..192
    const int wn = (warp & 3) * 32;

#pragma unroll
    for (int mi = 0; mi < 4; mi++)
#pragma unroll
        for (int ni = 0; ni < 4; ni++)
#pragma unroll
            for (int r = 0; r < 4; r++) c[mi][ni][r] = 0.f;

    gemm_stage(smb, 0, Ag, Bg, bm, bn, 0, tid);
    CP_COMMIT();
    gemm_stage(smb, 1, Ag, Bg, bm, bn, 64, tid);
    CP_COMMIT();

    const int a_r = (lmat & 1) * 8 + lrow;
    const int b_r = (lmat >> 1) * 8 + lrow;
    const int a_cb = lmat >> 1;
    const int b_cb = lmat & 1;

    int cb = 0, sb = 2;
    const int NT = Dn / 64;   // 16
    for (int t = 0; t < NT; t++) {
        CP_WAIT(1);
        __syncthreads();
        if (t + 2 < NT)
            gemm_stage(smb, sb, Ag, Bg, bm, bn, (t + 2) * 64, tid);
        CP_COMMIT();

        const uint32_t sbase = smb + cb * GSTAGE;
#pragma unroll
        for (int ks = 0; ks < 4; ks++) {
            const uint32_t aoff = (uint32_t)((ks >> 1) * 16384);
            const uint32_t boff = 32768u + (uint32_t)((ks >> 1) * 8192);
            const int kk = ks & 1;
            uint32_t ah[4][4];
#pragma unroll
            for (int mi = 0; mi < 4; mi++) {
                const int row = wm + mi * 16 + a_r;
                const int cc = (kk * 2 + a_cb) ^ ((row >> 1) & 3);
                ldmx4(ah[mi], sbase + aoff + (uint32_t)(row * 64 + cc * 16));
            }
#pragma unroll
            for (int p = 0; p < 2; p++) {
                const int row = wn + p * 16 + b_r;
                const int cc = (kk * 2 + b_cb) ^ ((row >> 1) & 3);
                uint32_t bh4[4];
                ldmx4(bh4, sbase + boff + (uint32_t)(row * 64 + cc * 16));
#pragma unroll
                for (int mi = 0; mi < 4; mi++) {
                    mma_f16(c[mi][2 * p],     ah[mi], bh4);
                    mma_f16(c[mi][2 * p + 1], ah[mi], bh4 + 2);
                }
            }
        }

        cb = (cb == 2) ? 0 : cb + 1;
        sb = (sb == 2) ? 0 : sb + 1;
    }
}

// ---- projection GEMM: z = 0(Q, scaled by 0.125*log2e) / 1(K) / 2(Vt) ----
__global__ __launch_bounds__(512, 1)
void gemm_proj(const float* __restrict__ bq, const float* __restrict__ bk,
               const float* __restrict__ bv)
{
    extern __shared__ char sm[];
    const uint32_t smb = smem_u32(sm);
    const int tid = threadIdx.x;
    const int z = blockIdx.z;
    const int bm = blockIdx.y * 256;
    const int bn = blockIdx.x * 128;
    const float* bias = (z == 0) ? bq : (z == 1) ? bk : bv;

    float c[4][4][4];
    gemm_main(smb, gx[z], gw[z], bm, bn, tid, c);

    const int lane = tid & 31;
    const int warp = tid >> 5;
    const int g  = lane >> 2;
    const int t2 = (lane & 3) * 2;
    const int wm = (warp >> 2) * 64;
    const int wn = (warp & 3) * 32;
    const float QS = 0.125f * 1.4426950408889634f;   // fold log2(e) into Q

#pragma unroll
    for (int mi = 0; mi < 4; mi++) {
        const int row0 = bm + wm + mi * 16 + g;
        const int b  = row0 >> 11;
        const int s0 = row0 & (Sn - 1);
#pragma unroll
        for (int ni = 0; ni < 4; ni++) {
            const int col = bn + wn + ni * 8 + t2;
            const int h = col >> 6, e = col & 63;
            float v00 = c[mi][ni][0] + bias[col];
            float v01 = c[mi][ni][1] + bias[col + 1];
            float v10 = c[mi][ni][2] + bias[col];
            float v11 = c[mi][ni][3] + bias[col + 1];
            if (z == 0) { v00 *= QS; v01 *= QS; v10 *= QS; v11 *= QS; }
            const size_t r0 = ((size_t)(b * Hn + h) * Sn + s0) * HD + e;
            if (z == 0) {
                *(uint32_t*)(gQ + r0)          = pack_f16(v00, v01);
                *(uint32_t*)(gQ + r0 + 8 * HD) = pack_f16(v10, v11);
            } else if (z == 1) {
                *(uint32_t*)(gK + r0)          = pack_f16(v00, v01);
                *(uint32_t*)(gK + r0 + 8 * HD) = pack_f16(v10, v11);
            } else {
                // V transposed, fp16: Vt[(b*Hn+h)*64 + e][s]
                const size_t base = ((size_t)(b * Hn + h) * HD + e) * Sn;
                gVt[base + s0]          = __float2half_rn(v00);
                gVt[base + Sn + s0]     = __float2half_rn(v01);
                gVt[base + s0 + 8]      = __float2half_rn(v10);
                gVt[base + Sn + s0 + 8] = __float2half_rn(v11);
            }
        }
    }
}

// ---- final GEMM: cat @ Wo + bo -> out (f32) ----
__global__ __launch_bounds__(512, 1)
void gemm_out(const float* __restrict__ bo, float* __restrict__ out)
{
    extern __shared__ char sm[];
    const uint32_t smb = smem_u32(sm);
    const int tid = threadIdx.x;
    const int bm = blockIdx.y * 256;
    const int bn = blockIdx.x * 128;

    float c[4][4][4];
    gemm_main(smb, gC, gwo, bm, bn, tid, c);

    const int lane = tid & 31;
    const int warp = tid >> 5;
    const int g  = lane >> 2;
    const int t2 = (lane & 3) * 2;
    const int wm = (warp >> 2) * 64;
    const int wn = (warp & 3) * 32;

#pragma unroll
    for (int mi = 0; mi < 4; mi++) {
        const int row0 = bm + wm + mi * 16 + g;
#pragma unroll
        for (int ni = 0; ni < 4; ni++) {
            const int col = bn + wn + ni * 8 + t2;
            const float b0v = bo[col], b1v = bo[col + 1];
            *(float2*)(out + (size_t)row0 * Dn + col) =
                make_float2(c[mi][ni][0] + b0v, c[mi][ni][1] + b1v);
            *(float2*)(out + (size_t)(row0 + 8) * Dn + col) =
                make_float2(c[mi][ni][2] + b0v, c[mi][ni][3] + b1v);
        }
    }
}

// ===========================================================================
// Flash attention, no-rescale softmax. 256 q-rows per CTA (two 128-row
// q-blocks SHARING every K/V fragment), 8 warps, K-tile 64, 3-stage ring.
// Pure fp16 MMAs; exp via ex2.approx.f16x2; row sums via HADD2 trees on
// the packed fp16 P pairs (no tensor-pipe cost; fma/alu pipes are idle).
// Stage: K[64x64]fp16 pad 144B/row @0 (9216B), Vt same @9216. Stride 18432.
// ===========================================================================
#define AST 18432
#define ATTN_SMEM (3 * AST)

__device__ __forceinline__ void attn_stage(uint32_t smb, int buf, int bh,
                                           int kt, int tid)
{
    const uint32_t b0 = smb + buf * AST;
#pragma unroll
    for (int i = 0; i < 4; i++) {
        const int idx = i * 256 + tid;      // 0..1023
        const int arr = idx >> 9;           // 0=K, 1=V
        const int cidx = idx & 511;
        const int row = cidx >> 3;          // 0..63
        const int ch  = cidx & 7;
        const uint32_t dst = b0 + arr * 9216 + row * 144 + ch * 16;
        const hf* g = arr ? (gVt + ((size_t)bh * HD + row) * Sn + kt + ch * 8)
                          : (gK  + ((size_t)bh * Sn + kt + row) * HD + ch * 8);
        CP16(dst, g);
    }
}

__global__ __launch_bounds__(256, 1)
void attn_mma()
{
    extern __shared__ char sm[];
    const uint32_t smb = smem_u32(sm);
    const int tid  = threadIdx.x;
    const int lane = tid & 31;
    const int warp = tid >> 5;
    const int g  = lane >> 2;
    const int t2 = (lane & 3) * 2;
    const int lrow = lane & 7;
    const int lmat = lane >> 3;
    const int bh = blockIdx.y;
    const int q0 = blockIdx.x * 256;
    const int mr = warp * 16;

    // ---- Q fragments for both q-blocks (q0, q0+128) ----
    uint32_t qh[2][4][4];
#pragma unroll
    for (int blk = 0; blk < 2; blk++) {
        const hf* h0 = gQ + ((size_t)bh * Sn + q0 + blk * 128 + mr + g) * HD;
        const hf* h1 = h0 + 8 * HD;
#pragma unroll
        for (int ks = 0; ks < 4; ks++) {
            const int kc = ks * 16 + t2;
            qh[blk][ks][0] = *(const uint32_t*)(h0 + kc);
            qh[blk][ks][1] = *(const uint32_t*)(h1 + kc);
            qh[blk][ks][2] = *(const uint32_t*)(h0 + kc + 8);
            qh[blk][ks][3] = *(const uint32_t*)(h1 + kc + 8);
        }
    }

    float O0[8][4], O1[8][4];
#pragma unroll
    for (int ef = 0; ef < 8; ef++)
#pragma unroll
        for (int r = 0; r < 4; r++) { O0[ef][r] = 0.f; O1[ef][r] = 0.f; }
    float rs[4] = {0.f, 0.f, 0.f, 0.f};   // {b0 row g, b0 row g+8, b1 g, b1 g+8}

    attn_stage(smb, 0, bh, 0, tid);
    CP_COMMIT();
    attn_stage(smb, 1, bh, 64, tid);
    CP_COMMIT();

    const uint32_t row_off = (uint32_t)(((lmat >> 1) * 8 + lrow) * 144);

    int cb = 0;
    int sb = 2;
    const int NT = Sn / 64;   // 32
    for (int t = 0; t < NT; t++) {
        CP_WAIT(1);
        __syncthreads();
        if (t + 2 < NT) attn_stage(smb, sb, bh, (t + 2) * 64, tid);
        CP_COMMIT();

        const uint32_t kbase = smb + cb * AST;
        const uint32_t vbase = kbase + 9216;

        // ---- S = Q K^T for BOTH q-blocks per K fragment ----
        float sc0[8][4], sc1[8][4];
#pragma unroll
        for (int nf = 0; nf < 8; nf++)
#pragma unroll
            for (int r = 0; r < 4; r++) { sc0[nf][r] = 0.f; sc1[nf][r] = 0.f; }

#pragma unroll
        for (int ks = 0; ks < 4; ks++) {
            const uint32_t kcol = (uint32_t)((ks * 16 + (lmat & 1) * 8) * 2);
#pragma unroll
            for (int p = 0; p < 4; p++) {
                const uint32_t ka = kbase + (uint32_t)(p * 2304) + row_off + kcol;
                uint32_t kh4[4];
                ldmx4(kh4, ka);
                mma_f16(sc0[2 * p],     qh[0][ks], kh4);
                mma_f16(sc0[2 * p + 1], qh[0][ks], kh4 + 2);
                mma_f16(sc1[2 * p],     qh[1][ks], kh4);
                mma_f16(sc1[2 * p + 1], qh[1][ks], kh4 + 2);
            }
        }

        // ---- P = 2^sc (f16x2); row sums via HADD2 trees (fma/alu pipes) ----
        uint32_t ph0[4][4], ph1[4][4];
#pragma unroll
        for (int ks2 = 0; ks2 < 4; ks2++) {
            ph0[ks2][0] = ex2_h2(pack_f16(sc0[2 * ks2][0],     sc0[2 * ks2][1]));
            ph0[ks2][1] = ex2_h2(pack_f16(sc0[2 * ks2][2],     sc0[2 * ks2][3]));
            ph0[ks2][2] = ex2_h2(pack_f16(sc0[2 * ks2 + 1][0], sc0[2 * ks2 + 1][1]));
            ph0[ks2][3] = ex2_h2(pack_f16(sc0[2 * ks2 + 1][2], sc0[2 * ks2 + 1][3]));
            ph1[ks2][0] = ex2_h2(pack_f16(sc1[2 * ks2][0],     sc1[2 * ks2][1]));
            ph1[ks2][1] = ex2_h2(pack_f16(sc1[2 * ks2][2],     sc1[2 * ks2][3]));
            ph1[ks2][2] = ex2_h2(pack_f16(sc1[2 * ks2 + 1][0], sc1[2 * ks2 + 1][1]));
            ph1[ks2][3] = ex2_h2(pack_f16(sc1[2 * ks2 + 1][2], sc1[2 * ks2 + 1][3]));
        }
        rs[0] += psum(ph0, 0, 2);
        rs[1] += psum(ph0, 1, 3);
        rs[2] += psum(ph1, 0, 2);
        rs[3] += psum(ph1, 1, 3);

        // ---- O += P V for BOTH q-blocks per V fragment ----
#pragma unroll
        for (int ks2 = 0; ks2 < 4; ks2++) {
            const uint32_t vcol = (uint32_t)((ks2 * 16 + (lmat & 1) * 8) * 2);
#pragma unroll
            for (int p = 0; p < 4; p++) {
                const uint32_t va = vbase + (uint32_t)(p * 2304) + row_off + vcol;
                uint32_t vh4[4];
                ldmx4(vh4, va);
                mma_f16(O0[2 * p],     ph0[ks2], vh4);
                mma_f16(O0[2 * p + 1], ph0[ks2], vh4 + 2);
                mma_f16(O1[2 * p],     ph1[ks2], vh4);
                mma_f16(O1[2 * p + 1], ph1[ks2], vh4 + 2);
            }
        }

        cb = (cb == 2) ? 0 : cb + 1;
        sb = (sb == 2) ? 0 : sb + 1;
    }

    // ---- reduce row sums across the 4 lanes sharing a row ----
#pragma unroll
    for (int i = 0; i < 4; i++) {
        rs[i] += __shfl_xor_sync(0xffffffffu, rs[i], 1);
        rs[i] += __shfl_xor_sync(0xffffffffu, rs[i], 2);
    }

    // ---- normalize + write fp16 concat for both q-blocks ----
    const int b = bh >> 4;
    const int h = bh & 15;
#pragma unroll
    for (int blk = 0; blk < 2; blk++) {
        float (*O)[4] = blk ? O1 : O0;
        const float i0 = 1.f / rs[blk * 2];
        const float i1 = 1.f / rs[blk * 2 + 1];
        const int s0 = q0 + blk * 128 + mr + g;
        const size_t base0 = (size_t)(b * Sn + s0) * Dn + h * HD;
        const size_t base1 = (size_t)(b * Sn + s0 + 8) * Dn + h * HD;
#pragma unroll
        for (int ef = 0; ef < 8; ef++) {
            const int e = ef * 8 + t2;
            *(uint32_t*)(gC + base0 + e) = pack_f16(O[ef][0] * i0, O[ef][1] * i0);
            *(uint32_t*)(gC + base1 + e) = pack_f16(O[ef][2] * i1, O[ef][3] * i1);
        }
    }
}

// ---------------------------------------------------------------------------
extern "C" void kernel_launch(void* const* d_in, const int* in_sizes, int n_in,
                              void* d_out, int out_size)
{
    const float* q  = (const float*)d_in[0];
    const float* k  = (const float*)d_in[1];
    const float* v  = (const float*)d_in[2];
    const float* Wq = (const float*)d_in[3];
    const float* bq = (const float*)d_in[4];
    const float* Wk = (const float*)d_in[5];
    const float* bk = (const float*)d_in[6];
    const float* Wv = (const float*)d_in[7];
    const float* bv = (const float*)d_in[8];
    const float* Wo = (const float*)d_in[9];
    const float* bo = (const float*)d_in[10];
    float* out = (float*)d_out;

    cudaFuncSetAttribute(gemm_proj,
                         cudaFuncAttributeMaxDynamicSharedMemorySize, GEMM_SMEM);
    cudaFuncSetAttribute(gemm_out,
                         cudaFuncAttributeMaxDynamicSharedMemorySize, GEMM_SMEM);
    cudaFuncSetAttribute(attn_mma,
                         cudaFuncAttributeMaxDynamicSharedMemorySize, ATTN_SMEM);

    // 1) one-time conversions
    conv_in<<<dim3(MK / 8 / 256, 1, 3), 256>>>(q, k, v);
    conv_w<<<dim3(1024, 1, 4), 256>>>(Wq, Wk, Wv, Wo);

    // 2) fused Q/K/V projections (grid.z selects head path), 256x128 tiles
    gemm_proj<<<dim3(8, 16, 3), 512, GEMM_SMEM>>>(bq, bk, bv);

    // 3) attention (256 q-rows per CTA)
    attn_mma<<<dim3(Sn / 256, Bn * Hn), 256, ATTN_SMEM>>>();

    // 4) output projection
    gemm_out<<<dim3(8, 16), 512, GEMM_SMEM>>>(bo, out);
}

// round 14
// speedup vs baseline: 1.0316x; 1.0316x over previous
#include <cuda_runtime.h>
#include <cuda_fp16.h>
#include <cstdint>

// Problem constants
#define Bn 2
#define Sn 2048
#define Dn 1024
#define Hn 16
#define HD 64
#define Mt (Bn * Sn)        // 4096
#define MK (Mt * Dn)        // 4194304
#define NK (Dn * Dn)        // 1048576

typedef __half hf;

// ---------------- scratch (__device__ globals; no allocs) ----------------
__device__ hf gx[3][MK];                  // fp16 inputs q,k,v  [m][k]
__device__ hf gw[3][NK];                  // Wq/Wk/Wv as Bt [n][k], fp16
__device__ hf gwo[NK];                    // Wo as Bt [n][k], fp16
__device__ hf gQ[MK];                     // Q proj (scaled by 0.125*log2e)
__device__ hf gK[MK];                     // K proj, fp16 [bh*Sn+s][64]
__device__ hf gVt[MK];                    // V proj transposed, fp16 [bh*64+e][Sn]
__device__ hf gC[MK];                     // attention out (cat) fp16 [m][1024]

// ---------------- helpers ----------------
__device__ __forceinline__ uint32_t smem_u32(const void* p) {
    uint32_t a;
    asm("{ .reg .u64 t; cvta.to.shared.u64 t, %1; cvt.u32.u64 %0, t; }"
        : "=r"(a) : "l"(p));
    return a;
}
__device__ __forceinline__ uint32_t pack_f16(float x, float y) {
    uint32_t r;
    asm("cvt.rn.f16x2.f32 %0, %1, %2;" : "=r"(r) : "f"(y), "f"(x));
    return r;   // low half = x, high half = y
}
__device__ __forceinline__ uint32_t ex2_h2(uint32_t x) {
    uint32_t r;
    asm("ex2.approx.f16x2 %0, %1;" : "=r"(r) : "r"(x));
    return r;
}
__device__ __forceinline__ void mma_f16(float* c, const uint32_t* a, const uint32_t* b) {
    asm volatile(
        "mma.sync.aligned.m16n8k16.row.col.f32.f16.f16.f32 "
        "{%0,%1,%2,%3}, {%4,%5,%6,%7}, {%8,%9}, {%0,%1,%2,%3};"
        : "+f"(c[0]), "+f"(c[1]), "+f"(c[2]), "+f"(c[3])
        : "r"(a[0]), "r"(a[1]), "r"(a[2]), "r"(a[3]), "r"(b[0]), "r"(b[1]));
}
__device__ __forceinline__ void ldmx4(uint32_t* r, uint32_t a) {
    asm volatile("ldmatrix.sync.aligned.m8n8.x4.shared.b16 {%0,%1,%2,%3}, [%4];"
        : "=r"(r[0]), "=r"(r[1]), "=r"(r[2]), "=r"(r[3]) : "r"(a));
}
#define CP16(dst_u32, src_gptr) \
    asm volatile("cp.async.cg.shared.global [%0], [%1], 16;" \
        :: "r"(dst_u32), "l"(src_gptr))
#define CP_COMMIT() asm volatile("cp.async.commit_group;" ::: "memory")
#define CP_WAIT(n)  asm volatile("cp.async.wait_group %0;" :: "n"(n) : "memory")

// ===========================================================================
// Conversion kernels (run once per launch; memory-bound)
// ===========================================================================
__global__ __launch_bounds__(256)
void conv_in(const float* __restrict__ q, const float* __restrict__ k,
             const float* __restrict__ v)
{
    const int z = blockIdx.z;
    const float* src = (z == 0) ? q : (z == 1) ? k : v;
    hf* d = gx[z];
    const size_t i = ((size_t)blockIdx.x * 256 + threadIdx.x) * 8;
    const float4 a  = *(const float4*)(src + i);
    const float4 b2 = *(const float4*)(src + i + 4);
    uint32_t h[4];
    h[0] = pack_f16(a.x,  a.y);
    h[1] = pack_f16(a.z,  a.w);
    h[2] = pack_f16(b2.x, b2.y);
    h[3] = pack_f16(b2.z, b2.w);
    *(uint4*)(d + i) = *(uint4*)h;
}

__global__ __launch_bounds__(256)
void conv_w(const float* __restrict__ Wq, const float* __restrict__ Wk,
            const float* __restrict__ Wv, const float* __restrict__ Wo)
{
    const int z = blockIdx.z;
    const int idx = blockIdx.x * 256 + threadIdx.x;   // 262144 per z
    if (z < 3) {
        const float* W = (z == 0) ? Wq : (z == 1) ? Wk : Wv;   // [H][K][64]
        const int e4 = (idx & 15) * 4;
        const int hk = idx >> 4;
        const int h = hk >> 10, k = hk & 1023;
        const float4 w = *(const float4*)(W + ((size_t)h * Dn + k) * HD + e4);
        const float wv[4] = {w.x, w.y, w.z, w.w};
#pragma unroll
        for (int j = 0; j < 4; j++)
            gw[z][(size_t)(h * HD + e4 + j) * Dn + k] = __float2half_rn(wv[j]);
    } else {                                           // Wo [K=1024][N=1024]
        const int n4 = (idx & 255) * 4;
        const int k  = idx >> 8;
        const float4 w = *(const float4*)(Wo + (size_t)k * Dn + n4);
        const float wv[4] = {w.x, w.y, w.z, w.w};
#pragma unroll
        for (int j = 0; j < 4; j++)
            gwo[(size_t)(n4 + j) * Dn + k] = __float2half_rn(wv[j]);
    }
}

// ===========================================================================
// GEMM mainloop: 128x128 CTA tile, 128 threads = 4 warps (2m x 2n),
// warp tile 64x64 (MMA:ldmatrix ratio 4). K-step 64 (two 32-k swizzled
// subtiles). Pure fp16. 3-stage cp.async ring, ONE __syncthreads per
// K-tile. 2 CTAs/SM for cross-CTA latency overlap.
// Stage: A @0 (16KB: sub0 @0, sub1 @8192), B @16384 (16KB) = 32KB.
// ===========================================================================
#define GSTAGE 32768
#define GEMM_SMEM (3 * GSTAGE)

__device__ __forceinline__ void gemm_stage(uint32_t smb, int buf,
    const hf* Ag, const hf* Bg, int bm, int bn, int kt, int tid)
{
    const uint32_t b0 = smb + buf * GSTAGE;
#pragma unroll
    for (int i = 0; i < 16; i++) {
        const int idx = i * 128 + tid;   // 0..2047
        const int arr = idx >> 10;       // 0=A, 1=B
        const int cidx = idx & 1023;
        const int row = cidx >> 3;       // 0..127
        const int ch  = cidx & 7;        // 16B chunk (0..7)
        const int sub = ch >> 2;
        const int chs = (ch & 3) ^ ((row >> 1) & 3);
        const uint32_t dst = b0 + arr * 16384 + sub * 8192 + row * 64 + chs * 16;
        const hf* g = arr ? (Bg + (size_t)(bn + row) * Dn + kt + ch * 8)
                          : (Ag + (size_t)(bm + row) * Dn + kt + ch * 8);
        CP16(dst, g);
    }
}

__device__ __forceinline__ void gemm_main(uint32_t smb,
    const hf* Ag, const hf* Bg, int bm, int bn, int tid, float c[4][8][4])
{
    const int lane = tid & 31;
    const int warp = tid >> 5;           // 0..3
    const int lrow = lane & 7;
    const int lmat = lane >> 3;
    const int wm = (warp >> 1) * 64;
    const int wn = (warp & 1) * 64;

#pragma unroll
    for (int mi = 0; mi < 4; mi++)
#pragma unroll
        for (int ni = 0; ni < 8; ni++)
#pragma unroll
            for (int r = 0; r < 4; r++) c[mi][ni][r] = 0.f;

    gemm_stage(smb, 0, Ag, Bg, bm, bn, 0, tid);
    CP_COMMIT();
    gemm_stage(smb, 1, Ag, Bg, bm, bn, 64, tid);
    CP_COMMIT();

    const int a_r = (lmat & 1) * 8 + lrow;
    const int b_r = (lmat >> 1) * 8 + lrow;
    const int a_cb = lmat >> 1;
    const int b_cb = lmat & 1;

    int cb = 0, sb = 2;
    const int NT = Dn / 64;   // 16
    for (int t = 0; t < NT; t++) {
        CP_WAIT(1);
        __syncthreads();
        if (t + 2 < NT)
            gemm_stage(smb, sb, Ag, Bg, bm, bn, (t + 2) * 64, tid);
        CP_COMMIT();

        const uint32_t sbase = smb + cb * GSTAGE;
#pragma unroll
        for (int ks = 0; ks < 4; ks++) {
            const uint32_t soff = (uint32_t)((ks >> 1) * 8192);
            const int kk = ks & 1;
            uint32_t ah[4][4];
#pragma unroll
            for (int mi = 0; mi < 4; mi++) {
                const int row = wm + mi * 16 + a_r;
                const int cc = (kk * 2 + a_cb) ^ ((row >> 1) & 3);
                ldmx4(ah[mi], sbase + soff + (uint32_t)(row * 64 + cc * 16));
            }
#pragma unroll
            for (int p = 0; p < 4; p++) {
                const int row = wn + p * 16 + b_r;
                const int cc = (kk * 2 + b_cb) ^ ((row >> 1) & 3);
                uint32_t bh4[4];
                ldmx4(bh4, sbase + 16384 + soff + (uint32_t)(row * 64 + cc * 16));
#pragma unroll
                for (int mi = 0; mi < 4; mi++) {
                    mma_f16(c[mi][2 * p],     ah[mi], bh4);
                    mma_f16(c[mi][2 * p + 1], ah[mi], bh4 + 2);
                }
            }
        }

        cb = (cb == 2) ? 0 : cb + 1;
        sb = (sb == 2) ? 0 : sb + 1;
    }
}

// ---- projection GEMM: z = 0(Q, scaled by 0.125*log2e) / 1(K) / 2(Vt) ----
__global__ __launch_bounds__(128, 2)
void gemm_proj(const float* __restrict__ bq, const float* __restrict__ bk,
               const float* __restrict__ bv)
{
    extern __shared__ char sm[];
    const uint32_t smb = smem_u32(sm);
    const int tid = threadIdx.x;
    const int z = blockIdx.z;
    const int bm = blockIdx.y * 128;
    const int bn = blockIdx.x * 128;
    const float* bias = (z == 0) ? bq : (z == 1) ? bk : bv;

    float c[4][8][4];
    gemm_main(smb, gx[z], gw[z], bm, bn, tid, c);

    const int lane = tid & 31;
    const int warp = tid >> 5;
    const int g  = lane >> 2;
    const int t2 = (lane & 3) * 2;
    const int wm = (warp >> 1) * 64;
    const int wn = (warp & 1) * 64;
    const float QS = 0.125f * 1.4426950408889634f;   // fold log2(e) into Q

#pragma unroll
    for (int mi = 0; mi < 4; mi++) {
        const int row0 = bm + wm + mi * 16 + g;
        const int b  = row0 >> 11;
        const int s0 = row0 & (Sn - 1);
#pragma unroll
        for (int ni = 0; ni < 8; ni++) {
            const int col = bn + wn + ni * 8 + t2;
            const int h = col >> 6, e = col & 63;
            float v00 = c[mi][ni][0] + bias[col];
            float v01 = c[mi][ni][1] + bias[col + 1];
            float v10 = c[mi][ni][2] + bias[col];
            float v11 = c[mi][ni][3] + bias[col + 1];
            if (z == 0) { v00 *= QS; v01 *= QS; v10 *= QS; v11 *= QS; }
            const size_t r0 = ((size_t)(b * Hn + h) * Sn + s0) * HD + e;
            if (z == 0) {
                *(uint32_t*)(gQ + r0)          = pack_f16(v00, v01);
                *(uint32_t*)(gQ + r0 + 8 * HD) = pack_f16(v10, v11);
            } else if (z == 1) {
                *(uint32_t*)(gK + r0)          = pack_f16(v00, v01);
                *(uint32_t*)(gK + r0 + 8 * HD) = pack_f16(v10, v11);
            } else {
                // V transposed, fp16: Vt[(b*Hn+h)*64 + e][s]
                const size_t base = ((size_t)(b * Hn + h) * HD + e) * Sn;
                gVt[base + s0]          = __float2half_rn(v00);
                gVt[base + Sn + s0]     = __float2half_rn(v01);
                gVt[base + s0 + 8]      = __float2half_rn(v10);
                gVt[base + Sn + s0 + 8] = __float2half_rn(v11);
            }
        }
    }
}

// ---- final GEMM: cat @ Wo + bo -> out (f32) ----
__global__ __launch_bounds__(128, 2)
void gemm_out(const float* __restrict__ bo, float* __restrict__ out)
{
    extern __shared__ char sm[];
    const uint32_t smb = smem_u32(sm);
    const int tid = threadIdx.x;
    const int bm = blockIdx.y * 128;
    const int bn = blockIdx.x * 128;

    float c[4][8][4];
    gemm_main(smb, gC, gwo, bm, bn, tid, c);

    const int lane = tid & 31;
    const int warp = tid >> 5;
    const int g  = lane >> 2;
    const int t2 = (lane & 3) * 2;
    const int wm = (warp >> 1) * 64;
    const int wn = (warp & 1) * 64;

#pragma unroll
    for (int mi = 0; mi < 4; mi++) {
        const int row0 = bm + wm + mi * 16 + g;
#pragma unroll
        for (int ni = 0; ni < 8; ni++) {
            const int col = bn + wn + ni * 8 + t2;
            const float b0v = bo[col], b1v = bo[col + 1];
            *(float2*)(out + (size_t)row0 * Dn + col) =
                make_float2(c[mi][ni][0] + b0v, c[mi][ni][1] + b1v);
            *(float2*)(out + (size_t)(row0 + 8) * Dn + col) =
                make_float2(c[mi][ni][2] + b0v, c[mi][ni][3] + b1v);
        }
    }
}

// ===========================================================================
// Flash attention (R12 champion, unchanged). 256 q-rows per CTA (two
// 128-row q-blocks SHARING every K/V fragment), 8 warps, K-tile 64,
// 3-stage ring. Pure fp16 MMAs; exp via ex2.approx.f16x2; row sums via
// ones-column MMA. Stage: K[64x64] pad 144B/row @0, Vt @9216. Stride 18432.
// ===========================================================================
#define AST 18432
#define ATTN_SMEM (3 * AST)

__device__ __forceinline__ void attn_stage(uint32_t smb, int buf, int bh,
                                           int kt, int tid)
{
    const uint32_t b0 = smb + buf * AST;
#pragma unroll
    for (int i = 0; i < 4; i++) {
        const int idx = i * 256 + tid;      // 0..1023
        const int arr = idx >> 9;           // 0=K, 1=V
        const int cidx = idx & 511;
        const int row = cidx >> 3;          // 0..63
        const int ch  = cidx & 7;
        const uint32_t dst = b0 + arr * 9216 + row * 144 + ch * 16;
        const hf* g = arr ? (gVt + ((size_t)bh * HD + row) * Sn + kt + ch * 8)
                          : (gK  + ((size_t)bh * Sn + kt + row) * HD + ch * 8);
        CP16(dst, g);
    }
}

__global__ __launch_bounds__(256, 1)
void attn_mma()
{
    extern __shared__ char sm[];
    const uint32_t smb = smem_u32(sm);
    const int tid  = threadIdx.x;
    const int lane = tid & 31;
    const int warp = tid >> 5;
    const int g  = lane >> 2;
    const int t2 = (lane & 3) * 2;
    const int lrow = lane & 7;
    const int lmat = lane >> 3;
    const int bh = blockIdx.y;
    const int q0 = blockIdx.x * 256;
    const int mr = warp * 16;

    // ---- Q fragments for both q-blocks (q0, q0+128) ----
    uint32_t qh[2][4][4];
#pragma unroll
    for (int blk = 0; blk < 2; blk++) {
        const hf* h0 = gQ + ((size_t)bh * Sn + q0 + blk * 128 + mr + g) * HD;
        const hf* h1 = h0 + 8 * HD;
#pragma unroll
        for (int ks = 0; ks < 4; ks++) {
            const int kc = ks * 16 + t2;
            qh[blk][ks][0] = *(const uint32_t*)(h0 + kc);
            qh[blk][ks][1] = *(const uint32_t*)(h1 + kc);
            qh[blk][ks][2] = *(const uint32_t*)(h0 + kc + 8);
            qh[blk][ks][3] = *(const uint32_t*)(h1 + kc + 8);
        }
    }

    float O0[8][4], O1[8][4];
#pragma unroll
    for (int ef = 0; ef < 8; ef++)
#pragma unroll
        for (int r = 0; r < 4; r++) { O0[ef][r] = 0.f; O1[ef][r] = 0.f; }
    float rsum0[4] = {0.f, 0.f, 0.f, 0.f};
    float rsum1[4] = {0.f, 0.f, 0.f, 0.f};
    const uint32_t ones2[2] = {0x3C003C00u, 0x3C003C00u};

    attn_stage(smb, 0, bh, 0, tid);
    CP_COMMIT();
    attn_stage(smb, 1, bh, 64, tid);
    CP_COMMIT();

    const uint32_t row_off = (uint32_t)(((lmat >> 1) * 8 + lrow) * 144);

    int cb = 0;
    int sb = 2;
    const int NT = Sn / 64;   // 32
    for (int t = 0; t < NT; t++) {
        CP_WAIT(1);
        __syncthreads();
        if (t + 2 < NT) attn_stage(smb, sb, bh, (t + 2) * 64, tid);
        CP_COMMIT();

        const uint32_t kbase = smb + cb * AST;
        const uint32_t vbase = kbase + 9216;

        // ---- S = Q K^T for BOTH q-blocks per K fragment ----
        float sc0[8][4], sc1[8][4];
#pragma unroll
        for (int nf = 0; nf < 8; nf++)
#pragma unroll
            for (int r = 0; r < 4; r++) { sc0[nf][r] = 0.f; sc1[nf][r] = 0.f; }

#pragma unroll
        for (int ks = 0; ks < 4; ks++) {
            const uint32_t kcol = (uint32_t)((ks * 16 + (lmat & 1) * 8) * 2);
#pragma unroll
            for (int p = 0; p < 4; p++) {
                const uint32_t ka = kbase + (uint32_t)(p * 2304) + row_off + kcol;
                uint32_t kh4[4];
                ldmx4(kh4, ka);
                mma_f16(sc0[2 * p],     qh[0][ks], kh4);
                mma_f16(sc0[2 * p + 1], qh[0][ks], kh4 + 2);
                mma_f16(sc1[2 * p],     qh[1][ks], kh4);
                mma_f16(sc1[2 * p + 1], qh[1][ks], kh4 + 2);
            }
        }

        // ---- P = 2^sc (f16x2), row sums via ones-MMA ----
        uint32_t ph0[4][4], ph1[4][4];
#pragma unroll
        for (int ks2 = 0; ks2 < 4; ks2++) {
            ph0[ks2][0] = ex2_h2(pack_f16(sc0[2 * ks2][0],     sc0[2 * ks2][1]));
            ph0[ks2][1] = ex2_h2(pack_f16(sc0[2 * ks2][2],     sc0[2 * ks2][3]));
            ph0[ks2][2] = ex2_h2(pack_f16(sc0[2 * ks2 + 1][0], sc0[2 * ks2 + 1][1]));
            ph0[ks2][3] = ex2_h2(pack_f16(sc0[2 * ks2 + 1][2], sc0[2 * ks2 + 1][3]));
            ph1[ks2][0] = ex2_h2(pack_f16(sc1[2 * ks2][0],     sc1[2 * ks2][1]));
            ph1[ks2][1] = ex2_h2(pack_f16(sc1[2 * ks2][2],     sc1[2 * ks2][3]));
            ph1[ks2][2] = ex2_h2(pack_f16(sc1[2 * ks2 + 1][0], sc1[2 * ks2 + 1][1]));
            ph1[ks2][3] = ex2_h2(pack_f16(sc1[2 * ks2 + 1][2], sc1[2 * ks2 + 1][3]));
            mma_f16(rsum0, ph0[ks2], ones2);
            mma_f16(rsum1, ph1[ks2], ones2);
        }

        // ---- O += P V for BOTH q-blocks per V fragment ----
#pragma unroll
        for (int ks2 = 0; ks2 < 4; ks2++) {
            const uint32_t vcol = (uint32_t)((ks2 * 16 + (lmat & 1) * 8) * 2);
#pragma unroll
            for (int p = 0; p < 4; p++) {
                const uint32_t va = vbase + (uint32_t)(p * 2304) + row_off + vcol;
                uint32_t vh4[4];
                ldmx4(vh4, va);
                mma_f16(O0[2 * p],     ph0[ks2], vh4);
                mma_f16(O0[2 * p + 1], ph0[ks2], vh4 + 2);
                mma_f16(O1[2 * p],     ph1[ks2], vh4);
                mma_f16(O1[2 * p + 1], ph1[ks2], vh4 + 2);
            }
        }

        cb = (cb == 2) ? 0 : cb + 1;
        sb = (sb == 2) ? 0 : sb + 1;
    }

    // ---- normalize + write fp16 concat for both q-blocks ----
    const int b = bh >> 4;
    const int h = bh & 15;
#pragma unroll
    for (int blk = 0; blk < 2; blk++) {
        float (*O)[4] = blk ? O1 : O0;
        const float* rs = blk ? rsum1 : rsum0;
        const float i0 = 1.f / rs[0];
        const float i1 = 1.f / rs[2];
        const int s0 = q0 + blk * 128 + mr + g;
        const size_t base0 = (size_t)(b * Sn + s0) * Dn + h * HD;
        const size_t base1 = (size_t)(b * Sn + s0 + 8) * Dn + h * HD;
#pragma unroll
        for (int ef = 0; ef < 8; ef++) {
            const int e = ef * 8 + t2;
            *(uint32_t*)(gC + base0 + e) = pack_f16(O[ef][0] * i0, O[ef][1] * i0);
            *(uint32_t*)(gC + base1 + e) = pack_f16(O[ef][2] * i1, O[ef][3] * i1);
        }
    }
}

// ---------------------------------------------------------------------------
extern "C" void kernel_launch(void* const* d_in, const int* in_sizes, int n_in,
                              void* d_out, int out_size)
{
    const float* q  = (const float*)d_in[0];
    const float* k  = (const float*)d_in[1];
    const float* v  = (const float*)d_in[2];
    const float* Wq = (const float*)d_in[3];
    const float* bq = (const float*)d_in[4];
    const float* Wk = (const float*)d_in[5];
    const float* bk = (const float*)d_in[6];
    const float* Wv = (const float*)d_in[7];
    const float* bv = (const float*)d_in[8];
    const float* Wo = (const float*)d_in[9];
    const float* bo = (const float*)d_in[10];
    float* out = (float*)d_out;

    cudaFuncSetAttribute(gemm_proj,
                         cudaFuncAttributeMaxDynamicSharedMemorySize, GEMM_SMEM);
    cudaFuncSetAttribute(gemm_out,
                         cudaFuncAttributeMaxDynamicSharedMemorySize, GEMM_SMEM);
    cudaFuncSetAttribute(attn_mma,
                         cudaFuncAttributeMaxDynamicSharedMemorySize, ATTN_SMEM);

    // 1) one-time conversions
    conv_in<<<dim3(MK / 8 / 256, 1, 3), 256>>>(q, k, v);
    conv_w<<<dim3(1024, 1, 4), 256>>>(Wq, Wk, Wv, Wo);

    // 2) fused Q/K/V projections (grid.z selects head path), 128x128 tiles,
    //    4 warps x 64x64 warp tiles, 2 CTAs/SM
    gemm_proj<<<dim3(8, 32, 3), 128, GEMM_SMEM>>>(bq, bk, bv);

    // 3) attention (256 q-rows per CTA)
    attn_mma<<<dim3(Sn / 256, Bn * Hn), 256, ATTN_SMEM>>>();

    // 4) output projection
    gemm_out<<<dim3(8, 32), 128, GEMM_SMEM>>>(bo, out);
}

// round 15
// speedup vs baseline: 1.0623x; 1.0298x over previous
#include <cuda_runtime.h>
#include <cuda_fp16.h>
#include <cstdint>

// Problem constants
#define Bn 2
#define Sn 2048
#define Dn 1024
#define Hn 16
#define HD 64
#define Mt (Bn * Sn)        // 4096
#define MK (Mt * Dn)        // 4194304
#define NK (Dn * Dn)        // 1048576

typedef __half hf;

// ---------------- scratch (__device__ globals; no allocs) ----------------
__device__ hf gx[3][MK];                  // fp16 inputs q,k,v  [m][k]
__device__ hf gw[3][NK];                  // Wq/Wk/Wv as Bt [n][k], fp16
__device__ hf gwo[NK];                    // Wo as Bt [n][k], fp16
__device__ hf gQ[MK];                     // Q proj (scaled by 0.125*log2e)
__device__ hf gK[MK];                     // K proj, fp16 [bh*Sn+s][64]
__device__ hf gVt[MK];                    // V proj transposed, fp16 [bh*64+e][Sn]
__device__ hf gC[MK];                     // attention out (cat) fp16 [m][1024]

// ---------------- helpers ----------------
__device__ __forceinline__ uint32_t smem_u32(const void* p) {
    uint32_t a;
    asm("{ .reg .u64 t; cvta.to.shared.u64 t, %1; cvt.u32.u64 %0, t; }"
        : "=r"(a) : "l"(p));
    return a;
}
__device__ __forceinline__ uint32_t pack_f16(float x, float y) {
    uint32_t r;
    asm("cvt.rn.f16x2.f32 %0, %1, %2;" : "=r"(r) : "f"(y), "f"(x));
    return r;   // low half = x, high half = y
}
__device__ __forceinline__ uint32_t ex2_h2(uint32_t x) {
    uint32_t r;
    asm("ex2.approx.f16x2 %0, %1;" : "=r"(r) : "r"(x));
    return r;
}
__device__ __forceinline__ void mma_f16(float* c, const uint32_t* a, const uint32_t* b) {
    asm volatile(
        "mma.sync.aligned.m16n8k16.row.col.f32.f16.f16.f32 "
        "{%0,%1,%2,%3}, {%4,%5,%6,%7}, {%8,%9}, {%0,%1,%2,%3};"
        : "+f"(c[0]), "+f"(c[1]), "+f"(c[2]), "+f"(c[3])
        : "r"(a[0]), "r"(a[1]), "r"(a[2]), "r"(a[3]), "r"(b[0]), "r"(b[1]));
}
__device__ __forceinline__ void ldmx4(uint32_t* r, uint32_t a) {
    asm volatile("ldmatrix.sync.aligned.m8n8.x4.shared.b16 {%0,%1,%2,%3}, [%4];"
        : "=r"(r[0]), "=r"(r[1]), "=r"(r[2]), "=r"(r[3]) : "r"(a));
}
#define CP16(dst_u32, src_gptr) \
    asm volatile("cp.async.cg.shared.global [%0], [%1], 16;" \
        :: "r"(dst_u32), "l"(src_gptr))
#define CP_COMMIT() asm volatile("cp.async.commit_group;" ::: "memory")
#define CP_WAIT(n)  asm volatile("cp.async.wait_group %0;" :: "n"(n) : "memory")

// ===========================================================================
// Combined conversion kernel (one launch): z 0..2 inputs, z 3..6 weights.
// ===========================================================================
__global__ __launch_bounds__(256)
void conv_all(const float* __restrict__ q, const float* __restrict__ k,
              const float* __restrict__ v,
              const float* __restrict__ Wq, const float* __restrict__ Wk,
              const float* __restrict__ Wv, const float* __restrict__ Wo)
{
    const int z = blockIdx.z;
    if (z < 3) {
        const float* src = (z == 0) ? q : (z == 1) ? k : v;
        hf* d = gx[z];
        const size_t i = ((size_t)blockIdx.x * 256 + threadIdx.x) * 8;
        const float4 a  = *(const float4*)(src + i);
        const float4 b2 = *(const float4*)(src + i + 4);
        uint32_t h[4];
        h[0] = pack_f16(a.x,  a.y);
        h[1] = pack_f16(a.z,  a.w);
        h[2] = pack_f16(b2.x, b2.y);
        h[3] = pack_f16(b2.z, b2.w);
        *(uint4*)(d + i) = *(uint4*)h;
    } else {
        if (blockIdx.x >= 1024) return;
        const int zz = z - 3;
        const int idx = blockIdx.x * 256 + threadIdx.x;   // 0..262143
        if (zz < 3) {
            const float* W = (zz == 0) ? Wq : (zz == 1) ? Wk : Wv;  // [H][K][64]
            const int e4 = (idx & 15) * 4;
            const int hk = idx >> 4;
            const int h = hk >> 10, kk = hk & 1023;
            const float4 w = *(const float4*)(W + ((size_t)h * Dn + kk) * HD + e4);
            const float wv[4] = {w.x, w.y, w.z, w.w};
#pragma unroll
            for (int j = 0; j < 4; j++)
                gw[zz][(size_t)(h * HD + e4 + j) * Dn + kk] = __float2half_rn(wv[j]);
        } else {                                           // Wo [K][N]
            const int n4 = (idx & 255) * 4;
            const int kk = idx >> 8;
            const float4 w = *(const float4*)(Wo + (size_t)kk * Dn + n4);
            const float wv[4] = {w.x, w.y, w.z, w.w};
#pragma unroll
            for (int j = 0; j < 4; j++)
                gwo[(size_t)(n4 + j) * Dn + kk] = __float2half_rn(wv[j]);
        }
    }
}

// ===========================================================================
// GEMM (R12 champion): 128x128 CTA tile, 256 threads = 8 warps (2m x 4n),
// warp tile 64x32, K-step 64 (two 32-k swizzled subtiles per stage).
// Pure fp16, 3-stage cp.async ring, ONE __syncthreads per K-tile (16 iters),
// 2 CTAs/SM. Stage: A @0 (16KB), B @16384 (16KB) = 32KB.
// ===========================================================================
#define GSTAGE 32768
#define GEMM_SMEM (3 * GSTAGE)

__device__ __forceinline__ void gemm_stage(uint32_t smb, int buf,
    const hf* Ag, const hf* Bg, int bm, int bn, int kt, int tid)
{
    const uint32_t b0 = smb + buf * GSTAGE;
#pragma unroll
    for (int i = 0; i < 8; i++) {
        const int idx = i * 256 + tid;   // 0..2047
        const int arr = idx >> 10;       // 0=A, 1=B
        const int cidx = idx & 1023;
        const int row = cidx >> 3;       // 0..127
        const int ch  = cidx & 7;        // 16B chunk (0..7)
        const int sub = ch >> 2;
        const int chs = (ch & 3) ^ ((row >> 1) & 3);
        const uint32_t dst = b0 + arr * 16384 + sub * 8192 + row * 64 + chs * 16;
        const hf* g = arr ? (Bg + (size_t)(bn + row) * Dn + kt + ch * 8)
                          : (Ag + (size_t)(bm + row) * Dn + kt + ch * 8);
        CP16(dst, g);
    }
}

__device__ __forceinline__ void gemm_main(uint32_t smb,
    const hf* Ag, const hf* Bg, int bm, int bn, int tid, float c[4][4][4])
{
    const int lane = tid & 31;
    const int warp = tid >> 5;
    const int lrow = lane & 7;
    const int lmat = lane >> 3;
    const int wm = (warp >> 2) * 64;
    const int wn = (warp & 3) * 32;

#pragma unroll
    for (int mi = 0; mi < 4; mi++)
#pragma unroll
        for (int ni = 0; ni < 4; ni++)
#pragma unroll
            for (int r = 0; r < 4; r++) c[mi][ni][r] = 0.f;

    gemm_stage(smb, 0, Ag, Bg, bm, bn, 0, tid);
    CP_COMMIT();
    gemm_stage(smb, 1, Ag, Bg, bm, bn, 64, tid);
    CP_COMMIT();

    const int a_r = (lmat & 1) * 8 + lrow;
    const int b_r = (lmat >> 1) * 8 + lrow;
    const int a_cb = lmat >> 1;
    const int b_cb = lmat & 1;

    int cb = 0, sb = 2;
    const int NT = Dn / 64;   // 16
    for (int t = 0; t < NT; t++) {
        CP_WAIT(1);
        __syncthreads();
        if (t + 2 < NT)
            gemm_stage(smb, sb, Ag, Bg, bm, bn, (t + 2) * 64, tid);
        CP_COMMIT();

        const uint32_t sbase = smb + cb * GSTAGE;
#pragma unroll
        for (int ks = 0; ks < 4; ks++) {
            const uint32_t soff = (uint32_t)((ks >> 1) * 8192);
            const int kk = ks & 1;
            uint32_t ah[4][4];
#pragma unroll
            for (int mi = 0; mi < 4; mi++) {
                const int row = wm + mi * 16 + a_r;
                const int cc = (kk * 2 + a_cb) ^ ((row >> 1) & 3);
                ldmx4(ah[mi], sbase + soff + (uint32_t)(row * 64 + cc * 16));
            }
#pragma unroll
            for (int p = 0; p < 2; p++) {
                const int row = wn + p * 16 + b_r;
                const int cc = (kk * 2 + b_cb) ^ ((row >> 1) & 3);
                uint32_t bh4[4];
                ldmx4(bh4, sbase + 16384 + soff + (uint32_t)(row * 64 + cc * 16));
#pragma unroll
                for (int mi = 0; mi < 4; mi++) {
                    mma_f16(c[mi][2 * p],     ah[mi], bh4);
                    mma_f16(c[mi][2 * p + 1], ah[mi], bh4 + 2);
                }
            }
        }

        cb = (cb == 2) ? 0 : cb + 1;
        sb = (sb == 2) ? 0 : sb + 1;
    }
}

// ---- projection GEMM: z = 0(Q, scaled by 0.125*log2e) / 1(K) / 2(Vt) ----
__global__ __launch_bounds__(256, 2)
void gemm_proj(const float* __restrict__ bq, const float* __restrict__ bk,
               const float* __restrict__ bv)
{
    extern __shared__ char sm[];
    const uint32_t smb = smem_u32(sm);
    const int tid = threadIdx.x;
    const int z = blockIdx.z;
    const int bm = blockIdx.y * 128;
    const int bn = blockIdx.x * 128;
    const float* bias = (z == 0) ? bq : (z == 1) ? bk : bv;

    float c[4][4][4];
    gemm_main(smb, gx[z], gw[z], bm, bn, tid, c);

    const int lane = tid & 31;
    const int warp = tid >> 5;
    const int g  = lane >> 2;
    const int t2 = (lane & 3) * 2;
    const int wm = (warp >> 2) * 64;
    const int wn = (warp & 3) * 32;
    const float QS = 0.125f * 1.4426950408889634f;   // fold log2(e) into Q

#pragma unroll
    for (int mi = 0; mi < 4; mi++) {
        const int row0 = bm + wm + mi * 16 + g;
        const int b  = row0 >> 11;
        const int s0 = row0 & (Sn - 1);
#pragma unroll
        for (int ni = 0; ni < 4; ni++) {
            const int col = bn + wn + ni * 8 + t2;
            const int h = col >> 6, e = col & 63;
            float v00 = c[mi][ni][0] + bias[col];
            float v01 = c[mi][ni][1] + bias[col + 1];
            float v10 = c[mi][ni][2] + bias[col];
            float v11 = c[mi][ni][3] + bias[col + 1];
            if (z == 0) { v00 *= QS; v01 *= QS; v10 *= QS; v11 *= QS; }
            const size_t r0 = ((size_t)(b * Hn + h) * Sn + s0) * HD + e;
            if (z == 0) {
                *(uint32_t*)(gQ + r0)          = pack_f16(v00, v01);
                *(uint32_t*)(gQ + r0 + 8 * HD) = pack_f16(v10, v11);
            } else if (z == 1) {
                *(uint32_t*)(gK + r0)          = pack_f16(v00, v01);
                *(uint32_t*)(gK + r0 + 8 * HD) = pack_f16(v10, v11);
            } else {
                // V transposed, fp16: Vt[(b*Hn+h)*64 + e][s]
                const size_t base = ((size_t)(b * Hn + h) * HD + e) * Sn;
                gVt[base + s0]          = __float2half_rn(v00);
                gVt[base + Sn + s0]     = __float2half_rn(v01);
                gVt[base + s0 + 8]      = __float2half_rn(v10);
                gVt[base + Sn + s0 + 8] = __float2half_rn(v11);
            }
        }
    }
}

// ---- final GEMM: cat @ Wo + bo -> out (f32) ----
__global__ __launch_bounds__(256, 2)
void gemm_out(const float* __restrict__ bo, float* __restrict__ out)
{
    extern __shared__ char sm[];
    const uint32_t smb = smem_u32(sm);
    const int tid = threadIdx.x;
    const int bm = blockIdx.y * 128;
    const int bn = blockIdx.x * 128;

    float c[4][4][4];
    gemm_main(smb, gC, gwo, bm, bn, tid, c);

    const int lane = tid & 31;
    const int warp = tid >> 5;
    const int g  = lane >> 2;
    const int t2 = (lane & 3) * 2;
    const int wm = (warp >> 2) * 64;
    const int wn = (warp & 3) * 32;

#pragma unroll
    for (int mi = 0; mi < 4; mi++) {
        const int row0 = bm + wm + mi * 16 + g;
#pragma unroll
        for (int ni = 0; ni < 4; ni++) {
            const int col = bn + wn + ni * 8 + t2;
            const float b0v = bo[col], b1v = bo[col + 1];
            *(float2*)(out + (size_t)row0 * Dn + col) =
                make_float2(c[mi][ni][0] + b0v, c[mi][ni][1] + b1v);
            *(float2*)(out + (size_t)(row0 + 8) * Dn + col) =
                make_float2(c[mi][ni][2] + b0v, c[mi][ni][3] + b1v);
        }
    }
}

// ===========================================================================
// Flash attention, no-rescale softmax. 256 q-rows per CTA (two 128-row
// q-blocks sharing every K/V fragment), 8 warps, K-tile 128 processed as
// two 64-key sub-tiles (ONE barrier+wait per 128 keys), 3-stage ring.
// Softmax chunk ks2 interleaved directly with PV chunk ks2 (scheduler
// overlaps next chunk's ex2/pack with current chunk's MMAs); ph transient.
// Stage: K[128 rows x 64]fp16 pad 144B/row @0 (18432B),
//        Vt[64 rows x 128]fp16 pad 272B/row @18432 (17408B). Stride 35840.
// ===========================================================================
#define AST 35840
#define ATTN_SMEM (3 * AST)

__device__ __forceinline__ void attn_stage(uint32_t smb, int buf, int bh,
                                           int kt, int tid)
{
    const uint32_t b0 = smb + buf * AST;
#pragma unroll
    for (int i = 0; i < 8; i++) {
        const int idx = i * 256 + tid;      // 0..2047
        if (idx < 1024) {                   // K: 128 rows x 8 chunks
            const int row = idx >> 3;
            const int ch  = idx & 7;
            const uint32_t dst = b0 + row * 144 + ch * 16;
            const hf* g = gK + ((size_t)bh * Sn + kt + row) * HD + ch * 8;
            CP16(dst, g);
        } else {                            // V: 64 e-rows x 16 chunks (128 k)
            const int c2 = idx - 1024;
            const int row = c2 >> 4;
            const int ch  = c2 & 15;
            const uint32_t dst = b0 + 18432 + row * 272 + ch * 16;
            const hf* g = gVt + ((size_t)bh * HD + row) * Sn + kt + ch * 8;
            CP16(dst, g);
        }
    }
}

__global__ __launch_bounds__(256, 1)
void attn_mma()
{
    extern __shared__ char sm[];
    const uint32_t smb = smem_u32(sm);
    const int tid  = threadIdx.x;
    const int lane = tid & 31;
    const int warp = tid >> 5;
    const int g  = lane >> 2;
    const int t2 = (lane & 3) * 2;
    const int lrow = lane & 7;
    const int lmat = lane >> 3;
    const int bh = blockIdx.y;
    const int q0 = blockIdx.x * 256;
    const int mr = warp * 16;

    // ---- Q fragments for both q-blocks (q0, q0+128) ----
    uint32_t qh[2][4][4];
#pragma unroll
    for (int blk = 0; blk < 2; blk++) {
        const hf* h0 = gQ + ((size_t)bh * Sn + q0 + blk * 128 + mr + g) * HD;
        const hf* h1 = h0 + 8 * HD;
#pragma unroll
        for (int ks = 0; ks < 4; ks++) {
            const int kc = ks * 16 + t2;
            qh[blk][ks][0] = *(const uint32_t*)(h0 + kc);
            qh[blk][ks][1] = *(const uint32_t*)(h1 + kc);
            qh[blk][ks][2] = *(const uint32_t*)(h0 + kc + 8);
            qh[blk][ks][3] = *(const uint32_t*)(h1 + kc + 8);
        }
    }

    float O0[8][4], O1[8][4];
#pragma unroll
    for (int ef = 0; ef < 8; ef++)
#pragma unroll
        for (int r = 0; r < 4; r++) { O0[ef][r] = 0.f; O1[ef][r] = 0.f; }
    float rsum0[4] = {0.f, 0.f, 0.f, 0.f};
    float rsum1[4] = {0.f, 0.f, 0.f, 0.f};
    const uint32_t ones2[2] = {0x3C003C00u, 0x3C003C00u};

    attn_stage(smb, 0, bh, 0, tid);
    CP_COMMIT();
    attn_stage(smb, 1, bh, 128, tid);
    CP_COMMIT();

    const uint32_t krow_off = (uint32_t)(((lmat >> 1) * 8 + lrow) * 144);
    const uint32_t vrow_off = (uint32_t)(((lmat >> 1) * 8 + lrow) * 272);

    int cb = 0;
    int sb = 2;
    const int NT = Sn / 128;   // 16
    for (int t = 0; t < NT; t++) {
        CP_WAIT(1);
        __syncthreads();
        if (t + 2 < NT) attn_stage(smb, sb, bh, (t + 2) * 128, tid);
        CP_COMMIT();

        const uint32_t kbase = smb + cb * AST;
        const uint32_t vbase = kbase + 18432;

#pragma unroll
        for (int u = 0; u < 2; u++) {        // two 64-key sub-tiles
            const uint32_t ksub = kbase + (uint32_t)(u * 9216);   // 64 K rows

            // ---- S = Q K^T for BOTH q-blocks per K fragment ----
            float sc0[8][4], sc1[8][4];
#pragma unroll
            for (int nf = 0; nf < 8; nf++)
#pragma unroll
                for (int r = 0; r < 4; r++) { sc0[nf][r] = 0.f; sc1[nf][r] = 0.f; }

#pragma unroll
            for (int ks = 0; ks < 4; ks++) {
                const uint32_t kcol = (uint32_t)((ks * 16 + (lmat & 1) * 8) * 2);
#pragma unroll
                for (int p = 0; p < 4; p++) {
                    const uint32_t ka = ksub + (uint32_t)(p * 2304) + krow_off + kcol;
                    uint32_t kh4[4];
                    ldmx4(kh4, ka);
                    mma_f16(sc0[2 * p],     qh[0][ks], kh4);
                    mma_f16(sc0[2 * p + 1], qh[0][ks], kh4 + 2);
                    mma_f16(sc1[2 * p],     qh[1][ks], kh4);
                    mma_f16(sc1[2 * p + 1], qh[1][ks], kh4 + 2);
                }
            }

            // ---- softmax chunk + PV chunk interleaved (ph transient) ----
#pragma unroll
            for (int ks2 = 0; ks2 < 4; ks2++) {
                uint32_t ph0[4], ph1[4];
                ph0[0] = ex2_h2(pack_f16(sc0[2 * ks2][0],     sc0[2 * ks2][1]));
                ph0[1] = ex2_h2(pack_f16(sc0[2 * ks2][2],     sc0[2 * ks2][3]));
                ph0[2] = ex2_h2(pack_f16(sc0[2 * ks2 + 1][0], sc0[2 * ks2 + 1][1]));
                ph0[3] = ex2_h2(pack_f16(sc0[2 * ks2 + 1][2], sc0[2 * ks2 + 1][3]));
                ph1[0] = ex2_h2(pack_f16(sc1[2 * ks2][0],     sc1[2 * ks2][1]));
                ph1[1] = ex2_h2(pack_f16(sc1[2 * ks2][2],     sc1[2 * ks2][3]));
                ph1[2] = ex2_h2(pack_f16(sc1[2 * ks2 + 1][0], sc1[2 * ks2 + 1][1]));
                ph1[3] = ex2_h2(pack_f16(sc1[2 * ks2 + 1][2], sc1[2 * ks2 + 1][3]));
                mma_f16(rsum0, ph0, ones2);
                mma_f16(rsum1, ph1, ones2);
                const uint32_t vcol =
                    (uint32_t)(((u * 4 + ks2) * 16 + (lmat & 1) * 8) * 2);
#pragma unroll
                for (int p = 0; p < 4; p++) {
                    const uint32_t va = vbase + (uint32_t)(p * 4352) + vrow_off + vcol;
                    uint32_t vh4[4];
                    ldmx4(vh4, va);
                    mma_f16(O0[2 * p],     ph0, vh4);
                    mma_f16(O0[2 * p + 1], ph0, vh4 + 2);
                    mma_f16(O1[2 * p],     ph1, vh4);
                    mma_f16(O1[2 * p + 1], ph1, vh4 + 2);
                }
            }
        }

        cb = (cb == 2) ? 0 : cb + 1;
        sb = (sb == 2) ? 0 : sb + 1;
    }

    // ---- normalize + write fp16 concat for both q-blocks ----
    const int b = bh >> 4;
    const int h = bh & 15;
#pragma unroll
    for (int blk = 0; blk < 2; blk++) {
        float (*O)[4] = blk ? O1 : O0;
        const float* rs = blk ? rsum1 : rsum0;
        const float i0 = 1.f / rs[0];
        const float i1 = 1.f / rs[2];
        const int s0 = q0 + blk * 128 + mr + g;
        const size_t base0 = (size_t)(b * Sn + s0) * Dn + h * HD;
        const size_t base1 = (size_t)(b * Sn + s0 + 8) * Dn + h * HD;
#pragma unroll
        for (int ef = 0; ef < 8; ef++) {
            const int e = ef * 8 + t2;
            *(uint32_t*)(gC + base0 + e) = pack_f16(O[ef][0] * i0, O[ef][1] * i0);
            *(uint32_t*)(gC + base1 + e) = pack_f16(O[ef][2] * i1, O[ef][3] * i1);
        }
    }
}

// ---------------------------------------------------------------------------
extern "C" void kernel_launch(void* const* d_in, const int* in_sizes, int n_in,
                              void* d_out, int out_size)
{
    const float* q  = (const float*)d_in[0];
    const float* k  = (const float*)d_in[1];
    const float* v  = (const float*)d_in[2];
    const float* Wq = (const float*)d_in[3];
    const float* bq = (const float*)d_in[4];
    const float* Wk = (const float*)d_in[5];
    const float* bk = (const float*)d_in[6];
    const float* Wv = (const float*)d_in[7];
    const float* bv = (const float*)d_in[8];
    const float* Wo = (const float*)d_in[9];
    const float* bo = (const float*)d_in[10];
    float* out = (float*)d_out;

    cudaFuncSetAttribute(gemm_proj,
                         cudaFuncAttributeMaxDynamicSharedMemorySize, GEMM_SMEM);
    cudaFuncSetAttribute(gemm_out,
                         cudaFuncAttributeMaxDynamicSharedMemorySize, GEMM_SMEM);
    cudaFuncSetAttribute(attn_mma,
                         cudaFuncAttributeMaxDynamicSharedMemorySize, ATTN_SMEM);

    // 1) one-time conversions (single launch)
    conv_all<<<dim3(MK / 8 / 256, 1, 7), 256>>>(q, k, v, Wq, Wk, Wv, Wo);

    // 2) fused Q/K/V projections (grid.z selects head path)
    gemm_proj<<<dim3(8, 32, 3), 256, GEMM_SMEM>>>(bq, bk, bv);

    // 3) attention (256 q-rows per CTA, K-tile 128)
    attn_mma<<<dim3(Sn / 256, Bn * Hn), 256, ATTN_SMEM>>>();

    // 4) output projection
    gemm_out<<<dim3(8, 32), 256, GEMM_SMEM>>>(bo, out);
}

// round 16
// speedup vs baseline: 1.0674x; 1.0047x over previous
#include <cuda_runtime.h>
#include <cuda_fp16.h>
#include <cstdint>

// Problem constants
#define Bn 2
#define Sn 2048
#define Dn 1024
#define Hn 16
#define HD 64
#define Mt (Bn * Sn)        // 4096
#define MK (Mt * Dn)        // 4194304
#define NK (Dn * Dn)        // 1048576

typedef __half hf;

// ---------------- scratch (__device__ globals; no allocs) ----------------
__device__ hf gx[3][MK];                  // fp16 inputs q,k,v  [m][k]
__device__ hf gw[3][NK];                  // Wq/Wk/Wv as Bt [n][k], fp16
__device__ hf gwo[NK];                    // Wo as Bt [n][k], fp16
__device__ hf gQ[MK];                     // Q proj (scaled by 0.125*log2e)
__device__ hf gK[MK];                     // K proj, fp16 [bh*Sn+s][64]
__device__ hf gVt[MK];                    // V proj transposed, fp16 [bh*64+e][Sn]
__device__ hf gC[MK];                     // attention out (cat) fp16 [m][1024]

// ---------------- helpers ----------------
__device__ __forceinline__ uint32_t smem_u32(const void* p) {
    uint32_t a;
    asm("{ .reg .u64 t; cvta.to.shared.u64 t, %1; cvt.u32.u64 %0, t; }"
        : "=r"(a) : "l"(p));
    return a;
}
__device__ __forceinline__ uint32_t pack_f16(float x, float y) {
    uint32_t r;
    asm("cvt.rn.f16x2.f32 %0, %1, %2;" : "=r"(r) : "f"(y), "f"(x));
    return r;   // low half = x, high half = y
}
__device__ __forceinline__ uint32_t ex2_h2(uint32_t x) {
    uint32_t r;
    asm("ex2.approx.f16x2 %0, %1;" : "=r"(r) : "r"(x));
    return r;
}
__device__ __forceinline__ void mma_f16(float* c, const uint32_t* a, const uint32_t* b) {
    asm volatile(
        "mma.sync.aligned.m16n8k16.row.col.f32.f16.f16.f32 "
        "{%0,%1,%2,%3}, {%4,%5,%6,%7}, {%8,%9}, {%0,%1,%2,%3};"
        : "+f"(c[0]), "+f"(c[1]), "+f"(c[2]), "+f"(c[3])
        : "r"(a[0]), "r"(a[1]), "r"(a[2]), "r"(a[3]), "r"(b[0]), "r"(b[1]));
}
__device__ __forceinline__ void ldmx4(uint32_t* r, uint32_t a) {
    asm volatile("ldmatrix.sync.aligned.m8n8.x4.shared.b16 {%0,%1,%2,%3}, [%4];"
        : "=r"(r[0]), "=r"(r[1]), "=r"(r[2]), "=r"(r[3]) : "r"(a));
}
#define CP16(dst_u32, src_gptr) \
    asm volatile("cp.async.cg.shared.global [%0], [%1], 16;" \
        :: "r"(dst_u32), "l"(src_gptr))
#define CP_COMMIT() asm volatile("cp.async.commit_group;" ::: "memory")
#define CP_WAIT(n)  asm volatile("cp.async.wait_group %0;" :: "n"(n) : "memory")

// ===========================================================================
// Combined conversion kernel (one launch): z 0..2 inputs, z 3..6 weights.
// ===========================================================================
__global__ __launch_bounds__(256)
void conv_all(const float* __restrict__ q, const float* __restrict__ k,
              const float* __restrict__ v,
              const float* __restrict__ Wq, const float* __restrict__ Wk,
              const float* __restrict__ Wv, const float* __restrict__ Wo)
{
    const int z = blockIdx.z;
    if (z < 3) {
        const float* src = (z == 0) ? q : (z == 1) ? k : v;
        hf* d = gx[z];
        const size_t i = ((size_t)blockIdx.x * 256 + threadIdx.x) * 8;
        const float4 a  = *(const float4*)(src + i);
        const float4 b2 = *(const float4*)(src + i + 4);
        uint32_t h[4];
        h[0] = pack_f16(a.x,  a.y);
        h[1] = pack_f16(a.z,  a.w);
        h[2] = pack_f16(b2.x, b2.y);
        h[3] = pack_f16(b2.z, b2.w);
        *(uint4*)(d + i) = *(uint4*)h;
    } else {
        if (blockIdx.x >= 1024) return;
        const int zz = z - 3;
        const int idx = blockIdx.x * 256 + threadIdx.x;   // 0..262143
        if (zz < 3) {
            const float* W = (zz == 0) ? Wq : (zz == 1) ? Wk : Wv;  // [H][K][64]
            const int e4 = (idx & 15) * 4;
            const int hk = idx >> 4;
            const int h = hk >> 10, kk = hk & 1023;
            const float4 w = *(const float4*)(W + ((size_t)h * Dn + kk) * HD + e4);
            const float wv[4] = {w.x, w.y, w.z, w.w};
#pragma unroll
            for (int j = 0; j < 4; j++)
                gw[zz][(size_t)(h * HD + e4 + j) * Dn + kk] = __float2half_rn(wv[j]);
        } else {                                           // Wo [K][N]
            const int n4 = (idx & 255) * 4;
            const int kk = idx >> 8;
            const float4 w = *(const float4*)(Wo + (size_t)kk * Dn + n4);
            const float wv[4] = {w.x, w.y, w.z, w.w};
#pragma unroll
            for (int j = 0; j < 4; j++)
                gwo[(size_t)(n4 + j) * Dn + kk] = __float2half_rn(wv[j]);
        }
    }
}

// ===========================================================================
// GEMM (champion, at mma.sync dispatch ceiling): 128x128 CTA tile,
// 256 threads = 8 warps (2m x 4n), warp tile 64x32, K-step 64.
// 3-stage cp.async ring, ONE __syncthreads per K-tile, 2 CTAs/SM.
// Stage: A @0 (16KB), B @16384 (16KB) = 32KB.
// ===========================================================================
#define GSTAGE 32768
#define GEMM_SMEM (3 * GSTAGE)

__device__ __forceinline__ void gemm_stage(uint32_t smb, int buf,
    const hf* Ag, const hf* Bg, int bm, int bn, int kt, int tid)
{
    const uint32_t b0 = smb + buf * GSTAGE;
#pragma unroll
    for (int i = 0; i < 8; i++) {
        const int idx = i * 256 + tid;   // 0..2047
        const int arr = idx >> 10;       // 0=A, 1=B
        const int cidx = idx & 1023;
        const int row = cidx >> 3;       // 0..127
        const int ch  = cidx & 7;        // 16B chunk (0..7)
        const int sub = ch >> 2;
        const int chs = (ch & 3) ^ ((row >> 1) & 3);
        const uint32_t dst = b0 + arr * 16384 + sub * 8192 + row * 64 + chs * 16;
        const hf* g = arr ? (Bg + (size_t)(bn + row) * Dn + kt + ch * 8)
                          : (Ag + (size_t)(bm + row) * Dn + kt + ch * 8);
        CP16(dst, g);
    }
}

__device__ __forceinline__ void gemm_main(uint32_t smb,
    const hf* Ag, const hf* Bg, int bm, int bn, int tid, float c[4][4][4])
{
    const int lane = tid & 31;
    const int warp = tid >> 5;
    const int lrow = lane & 7;
    const int lmat = lane >> 3;
    const int wm = (warp >> 2) * 64;
    const int wn = (warp & 3) * 32;

#pragma unroll
    for (int mi = 0; mi < 4; mi++)
#pragma unroll
        for (int ni = 0; ni < 4; ni++)
#pragma unroll
            for (int r = 0; r < 4; r++) c[mi][ni][r] = 0.f;

    gemm_stage(smb, 0, Ag, Bg, bm, bn, 0, tid);
    CP_COMMIT();
    gemm_stage(smb, 1, Ag, Bg, bm, bn, 64, tid);
    CP_COMMIT();

    const int a_r = (lmat & 1) * 8 + lrow;
    const int b_r = (lmat >> 1) * 8 + lrow;
    const int a_cb = lmat >> 1;
    const int b_cb = lmat & 1;

    int cb = 0, sb = 2;
    const int NT = Dn / 64;   // 16
    for (int t = 0; t < NT; t++) {
        CP_WAIT(1);
        __syncthreads();
        if (t + 2 < NT)
            gemm_stage(smb, sb, Ag, Bg, bm, bn, (t + 2) * 64, tid);
        CP_COMMIT();

        const uint32_t sbase = smb + cb * GSTAGE;
#pragma unroll
        for (int ks = 0; ks < 4; ks++) {
            const uint32_t soff = (uint32_t)((ks >> 1) * 8192);
            const int kk = ks & 1;
            uint32_t ah[4][4];
#pragma unroll
            for (int mi = 0; mi < 4; mi++) {
                const int row = wm + mi * 16 + a_r;
                const int cc = (kk * 2 + a_cb) ^ ((row >> 1) & 3);
                ldmx4(ah[mi], sbase + soff + (uint32_t)(row * 64 + cc * 16));
            }
#pragma unroll
            for (int p = 0; p < 2; p++) {
                const int row = wn + p * 16 + b_r;
                const int cc = (kk * 2 + b_cb) ^ ((row >> 1) & 3);
                uint32_t bh4[4];
                ldmx4(bh4, sbase + 16384 + soff + (uint32_t)(row * 64 + cc * 16));
#pragma unroll
                for (int mi = 0; mi < 4; mi++) {
                    mma_f16(c[mi][2 * p],     ah[mi], bh4);
                    mma_f16(c[mi][2 * p + 1], ah[mi], bh4 + 2);
                }
            }
        }

        cb = (cb == 2) ? 0 : cb + 1;
        sb = (sb == 2) ? 0 : sb + 1;
    }
}

// ---- projection GEMM: z = 0(Q, scaled by 0.125*log2e) / 1(K) / 2(Vt) ----
__global__ __launch_bounds__(256, 2)
void gemm_proj(const float* __restrict__ bq, const float* __restrict__ bk,
               const float* __restrict__ bv)
{
    extern __shared__ char sm[];
    const uint32_t smb = smem_u32(sm);
    const int tid = threadIdx.x;
    const int z = blockIdx.z;
    const int bm = blockIdx.y * 128;
    const int bn = blockIdx.x * 128;
    const float* bias = (z == 0) ? bq : (z == 1) ? bk : bv;

    float c[4][4][4];
    gemm_main(smb, gx[z], gw[z], bm, bn, tid, c);

    const int lane = tid & 31;
    const int warp = tid >> 5;
    const int g  = lane >> 2;
    const int t2 = (lane & 3) * 2;
    const int wm = (warp >> 2) * 64;
    const int wn = (warp & 3) * 32;
    const float QS = 0.125f * 1.4426950408889634f;   // fold log2(e) into Q

#pragma unroll
    for (int mi = 0; mi < 4; mi++) {
        const int row0 = bm + wm + mi * 16 + g;
        const int b  = row0 >> 11;
        const int s0 = row0 & (Sn - 1);
#pragma unroll
        for (int ni = 0; ni < 4; ni++) {
            const int col = bn + wn + ni * 8 + t2;
            const int h = col >> 6, e = col & 63;
            float v00 = c[mi][ni][0] + bias[col];
            float v01 = c[mi][ni][1] + bias[col + 1];
            float v10 = c[mi][ni][2] + bias[col];
            float v11 = c[mi][ni][3] + bias[col + 1];
            if (z == 0) { v00 *= QS; v01 *= QS; v10 *= QS; v11 *= QS; }
            const size_t r0 = ((size_t)(b * Hn + h) * Sn + s0) * HD + e;
            if (z == 0) {
                *(uint32_t*)(gQ + r0)          = pack_f16(v00, v01);
                *(uint32_t*)(gQ + r0 + 8 * HD) = pack_f16(v10, v11);
            } else if (z == 1) {
                *(uint32_t*)(gK + r0)          = pack_f16(v00, v01);
                *(uint32_t*)(gK + r0 + 8 * HD) = pack_f16(v10, v11);
            } else {
                // V transposed, fp16: Vt[(b*Hn+h)*64 + e][s]
                const size_t base = ((size_t)(b * Hn + h) * HD + e) * Sn;
                gVt[base + s0]          = __float2half_rn(v00);
                gVt[base + Sn + s0]     = __float2half_rn(v01);
                gVt[base + s0 + 8]      = __float2half_rn(v10);
                gVt[base + Sn + s0 + 8] = __float2half_rn(v11);
            }
        }
    }
}

// ---- final GEMM: cat @ Wo + bo -> out (f32) ----
__global__ __launch_bounds__(256, 2)
void gemm_out(const float* __restrict__ bo, float* __restrict__ out)
{
    extern __shared__ char sm[];
    const uint32_t smb = smem_u32(sm);
    const int tid = threadIdx.x;
    const int bm = blockIdx.y * 128;
    const int bn = blockIdx.x * 128;

    float c[4][4][4];
    gemm_main(smb, gC, gwo, bm, bn, tid, c);

    const int lane = tid & 31;
    const int warp = tid >> 5;
    const int g  = lane >> 2;
    const int t2 = (lane & 3) * 2;
    const int wm = (warp >> 2) * 64;
    const int wn = (warp & 3) * 32;

#pragma unroll
    for (int mi = 0; mi < 4; mi++) {
        const int row0 = bm + wm + mi * 16 + g;
#pragma unroll
        for (int ni = 0; ni < 4; ni++) {
            const int col = bn + wn + ni * 8 + t2;
            const float b0v = bo[col], b1v = bo[col + 1];
            *(float2*)(out + (size_t)row0 * Dn + col) =
                make_float2(c[mi][ni][0] + b0v, c[mi][ni][1] + b1v);
            *(float2*)(out + (size_t)(row0 + 8) * Dn + col) =
                make_float2(c[mi][ni][2] + b0v, c[mi][ni][3] + b1v);
        }
    }
}

// ===========================================================================
// Flash attention, no-rescale softmax. 256 q-rows per CTA, 512 threads =
// 16 warps (4 warps/SMSP for MMA dispatch density), each warp owns its own
// 16 q-rows. K-tile 128 as two 64-key sub-tiles (one barrier per 128 keys),
// 3-stage ring. Pure fp16 MMAs; exp via ex2.approx.f16x2; row sums via
// ones-column MMA; softmax chunk interleaved with PV chunk.
// Stage: K[128 rows x 64]fp16 pad 144B/row @0 (18432B),
//        Vt[64 rows x 128]fp16 pad 272B/row @18432 (17408B). Stride 35840.
// ===========================================================================
#define AST 35840
#define ATTN_SMEM (3 * AST)

__device__ __forceinline__ void attn_stage(uint32_t smb, int buf, int bh,
                                           int kt, int tid)
{
    const uint32_t b0 = smb + buf * AST;
#pragma unroll
    for (int i = 0; i < 4; i++) {
        const int idx = i * 512 + tid;      // 0..2047
        if (idx < 1024) {                   // K: 128 rows x 8 chunks
            const int row = idx >> 3;
            const int ch  = idx & 7;
            const uint32_t dst = b0 + row * 144 + ch * 16;
            const hf* g = gK + ((size_t)bh * Sn + kt + row) * HD + ch * 8;
            CP16(dst, g);
        } else {                            // V: 64 e-rows x 16 chunks (128 k)
            const int c2 = idx - 1024;
            const int row = c2 >> 4;
            const int ch  = c2 & 15;
            const uint32_t dst = b0 + 18432 + row * 272 + ch * 16;
            const hf* g = gVt + ((size_t)bh * HD + row) * Sn + kt + ch * 8;
            CP16(dst, g);
        }
    }
}

__global__ __launch_bounds__(512, 1)
void attn_mma()
{
    extern __shared__ char sm[];
    const uint32_t smb = smem_u32(sm);
    const int tid  = threadIdx.x;
    const int lane = tid & 31;
    const int warp = tid >> 5;           // 0..15
    const int g  = lane >> 2;
    const int t2 = (lane & 3) * 2;
    const int lrow = lane & 7;
    const int lmat = lane >> 3;
    const int bh = blockIdx.y;
    const int q0 = blockIdx.x * 256;
    const int mr = warp * 16;            // warp's 16 q-rows

    // ---- Q fragments (this warp's rows only) ----
    uint32_t qh[4][4];
    {
        const hf* h0 = gQ + ((size_t)bh * Sn + q0 + mr + g) * HD;
        const hf* h1 = h0 + 8 * HD;
#pragma unroll
        for (int ks = 0; ks < 4; ks++) {
            const int kc = ks * 16 + t2;
            qh[ks][0] = *(const uint32_t*)(h0 + kc);
            qh[ks][1] = *(const uint32_t*)(h1 + kc);
            qh[ks][2] = *(const uint32_t*)(h0 + kc + 8);
            qh[ks][3] = *(const uint32_t*)(h1 + kc + 8);
        }
    }

    float O[8][4];
#pragma unroll
    for (int ef = 0; ef < 8; ef++)
#pragma unroll
        for (int r = 0; r < 4; r++) O[ef][r] = 0.f;
    float rsum[4] = {0.f, 0.f, 0.f, 0.f};
    const uint32_t ones2[2] = {0x3C003C00u, 0x3C003C00u};

    attn_stage(smb, 0, bh, 0, tid);
    CP_COMMIT();
    attn_stage(smb, 1, bh, 128, tid);
    CP_COMMIT();

    const uint32_t krow_off = (uint32_t)(((lmat >> 1) * 8 + lrow) * 144);
    const uint32_t vrow_off = (uint32_t)(((lmat >> 1) * 8 + lrow) * 272);

    int cb = 0;
    int sb = 2;
    const int NT = Sn / 128;   // 16
    for (int t = 0; t < NT; t++) {
        CP_WAIT(1);
        __syncthreads();
        if (t + 2 < NT) attn_stage(smb, sb, bh, (t + 2) * 128, tid);
        CP_COMMIT();

        const uint32_t kbase = smb + cb * AST;
        const uint32_t vbase = kbase + 18432;

#pragma unroll
        for (int u = 0; u < 2; u++) {        // two 64-key sub-tiles
            const uint32_t ksub = kbase + (uint32_t)(u * 9216);

            // ---- S = Q K^T (64 key cols) ----
            float sc[8][4];
#pragma unroll
            for (int nf = 0; nf < 8; nf++)
#pragma unroll
                for (int r = 0; r < 4; r++) sc[nf][r] = 0.f;

#pragma unroll
            for (int ks = 0; ks < 4; ks++) {
                const uint32_t kcol = (uint32_t)((ks * 16 + (lmat & 1) * 8) * 2);
#pragma unroll
                for (int p = 0; p < 4; p++) {
                    const uint32_t ka = ksub + (uint32_t)(p * 2304) + krow_off + kcol;
                    uint32_t kh4[4];
                    ldmx4(kh4, ka);
                    mma_f16(sc[2 * p],     qh[ks], kh4);
                    mma_f16(sc[2 * p + 1], qh[ks], kh4 + 2);
                }
            }

            // ---- softmax chunk + PV chunk interleaved (ph transient) ----
#pragma unroll
            for (int ks2 = 0; ks2 < 4; ks2++) {
                uint32_t ph[4];
                ph[0] = ex2_h2(pack_f16(sc[2 * ks2][0],     sc[2 * ks2][1]));
                ph[1] = ex2_h2(pack_f16(sc[2 * ks2][2],     sc[2 * ks2][3]));
                ph[2] = ex2_h2(pack_f16(sc[2 * ks2 + 1][0], sc[2 * ks2 + 1][1]));
                ph[3] = ex2_h2(pack_f16(sc[2 * ks2 + 1][2], sc[2 * ks2 + 1][3]));
                mma_f16(rsum, ph, ones2);
                const uint32_t vcol =
                    (uint32_t)(((u * 4 + ks2) * 16 + (lmat & 1) * 8) * 2);
#pragma unroll
                for (int p = 0; p < 4; p++) {
                    const uint32_t va = vbase + (uint32_t)(p * 4352) + vrow_off + vcol;
                    uint32_t vh4[4];
                    ldmx4(vh4, va);
                    mma_f16(O[2 * p],     ph, vh4);
                    mma_f16(O[2 * p + 1], ph, vh4 + 2);
                }
            }
        }

        cb = (cb == 2) ? 0 : cb + 1;
        sb = (sb == 2) ? 0 : sb + 1;
    }

    // ---- normalize + write fp16 concat ----
    const int b = bh >> 4;
    const int h = bh & 15;
    const float i0 = 1.f / rsum[0];
    const float i1 = 1.f / rsum[2];
    const int s0 = q0 + mr + g;
    const size_t base0 = (size_t)(b * Sn + s0) * Dn + h * HD;
    const size_t base1 = (size_t)(b * Sn + s0 + 8) * Dn + h * HD;
#pragma unroll
    for (int ef = 0; ef < 8; ef++) {
        const int e = ef * 8 + t2;
        *(uint32_t*)(gC + base0 + e) = pack_f16(O[ef][0] * i0, O[ef][1] * i0);
        *(uint32_t*)(gC + base1 + e) = pack_f16(O[ef][2] * i1, O[ef][3] * i1);
    }
}

// ---------------------------------------------------------------------------
extern "C" void kernel_launch(void* const* d_in, const int* in_sizes, int n_in,
                              void* d_out, int out_size)
{
    const float* q  = (const float*)d_in[0];
    const float* k  = (const float*)d_in[1];
    const float* v  = (const float*)d_in[2];
    const float* Wq = (const float*)d_in[3];
    const float* bq = (const float*)d_in[4];
    const float* Wk = (const float*)d_in[5];
    const float* bk = (const float*)d_in[6];
    const float* Wv = (const float*)d_in[7];
    const float* bv = (const float*)d_in[8];
    const float* Wo = (const float*)d_in[9];
    const float* bo = (const float*)d_in[10];
    float* out = (float*)d_out;

    cudaFuncSetAttribute(gemm_proj,
                         cudaFuncAttributeMaxDynamicSharedMemorySize, GEMM_SMEM);
    cudaFuncSetAttribute(gemm_out,
                         cudaFuncAttributeMaxDynamicSharedMemorySize, GEMM_SMEM);
    cudaFuncSetAttribute(attn_mma,
                         cudaFuncAttributeMaxDynamicSharedMemorySize, ATTN_SMEM);

    // 1) one-time conversions (single launch)
    conv_all<<<dim3(MK / 8 / 256, 1, 7), 256>>>(q, k, v, Wq, Wk, Wv, Wo);

    // 2) fused Q/K/V projections (grid.z selects head path)
    gemm_proj<<<dim3(8, 32, 3), 256, GEMM_SMEM>>>(bq, bk, bv);

    // 3) attention (256 q-rows per CTA, 512 threads, 4 warps/SMSP)
    attn_mma<<<dim3(Sn / 256, Bn * Hn), 512, ATTN_SMEM>>>();

    // 4) output projection
    gemm_out<<<dim3(8, 32), 256, GEMM_SMEM>>>(bo, out);
}

// round 17
// speedup vs baseline: 1.0967x; 1.0274x over previous
#include <cuda_runtime.h>
#include <cuda_fp16.h>
#include <cstdint>

// Problem constants
#define Bn 2
#define Sn 2048
#define Dn 1024
#define Hn 16
#define HD 64
#define Mt (Bn * Sn)        // 4096
#define MK (Mt * Dn)        // 4194304
#define NK (Dn * Dn)        // 1048576

typedef __half hf;

// ---------------- scratch (__device__ globals; no allocs) ----------------
__device__ hf gx[3][MK];                  // fp16 inputs q,k,v  [m][k]
__device__ hf gw[3][NK];                  // Wq/Wk/Wv as Bt [n][k], fp16
__device__ hf gwo[NK];                    // Wo as Bt [n][k], fp16
__device__ hf gQ[MK];                     // Q proj (scaled by 0.125*log2e)
__device__ hf gK[MK];                     // K proj, fp16 [bh*Sn+s][64]
__device__ hf gV[MK];                     // V proj, fp16 [bh*Sn+s][64] (row-major!)
__device__ hf gC[MK];                     // attention out (cat) fp16 [m][1024]

// ---------------- helpers ----------------
__device__ __forceinline__ uint32_t smem_u32(const void* p) {
    uint32_t a;
    asm("{ .reg .u64 t; cvta.to.shared.u64 t, %1; cvt.u32.u64 %0, t; }"
        : "=r"(a) : "l"(p));
    return a;
}
__device__ __forceinline__ uint32_t pack_f16(float x, float y) {
    uint32_t r;
    asm("cvt.rn.f16x2.f32 %0, %1, %2;" : "=r"(r) : "f"(y), "f"(x));
    return r;   // low half = x, high half = y
}
__device__ __forceinline__ uint32_t ex2_h2(uint32_t x) {
    uint32_t r;
    asm("ex2.approx.f16x2 %0, %1;" : "=r"(r) : "r"(x));
    return r;
}
__device__ __forceinline__ void mma_f16(float* c, const uint32_t* a, const uint32_t* b) {
    asm volatile(
        "mma.sync.aligned.m16n8k16.row.col.f32.f16.f16.f32 "
        "{%0,%1,%2,%3}, {%4,%5,%6,%7}, {%8,%9}, {%0,%1,%2,%3};"
        : "+f"(c[0]), "+f"(c[1]), "+f"(c[2]), "+f"(c[3])
        : "r"(a[0]), "r"(a[1]), "r"(a[2]), "r"(a[3]), "r"(b[0]), "r"(b[1]));
}
__device__ __forceinline__ void ldmx4(uint32_t* r, uint32_t a) {
    asm volatile("ldmatrix.sync.aligned.m8n8.x4.shared.b16 {%0,%1,%2,%3}, [%4];"
        : "=r"(r[0]), "=r"(r[1]), "=r"(r[2]), "=r"(r[3]) : "r"(a));
}
__device__ __forceinline__ void ldmx4t(uint32_t* r, uint32_t a) {
    asm volatile("ldmatrix.sync.aligned.m8n8.x4.trans.shared.b16 {%0,%1,%2,%3}, [%4];"
        : "=r"(r[0]), "=r"(r[1]), "=r"(r[2]), "=r"(r[3]) : "r"(a));
}
#define CP16(dst_u32, src_gptr) \
    asm volatile("cp.async.cg.shared.global [%0], [%1], 16;" \
        :: "r"(dst_u32), "l"(src_gptr))
#define CP_COMMIT() asm volatile("cp.async.commit_group;" ::: "memory")
#define CP_WAIT(n)  asm volatile("cp.async.wait_group %0;" :: "n"(n) : "memory")

// ===========================================================================
// Input conversion (coalesced both ways)
// ===========================================================================
__global__ __launch_bounds__(256)
void conv_in(const float* __restrict__ q, const float* __restrict__ k,
             const float* __restrict__ v)
{
    const int z = blockIdx.z;
    const float* src = (z == 0) ? q : (z == 1) ? k : v;
    hf* d = gx[z];
    const size_t i = ((size_t)blockIdx.x * 256 + threadIdx.x) * 8;
    const float4 a  = *(const float4*)(src + i);
    const float4 b2 = *(const float4*)(src + i + 4);
    uint32_t h[4];
    h[0] = pack_f16(a.x,  a.y);
    h[1] = pack_f16(a.z,  a.w);
    h[2] = pack_f16(b2.x, b2.y);
    h[3] = pack_f16(b2.z, b2.w);
    *(uint4*)(d + i) = *(uint4*)h;
}

// ===========================================================================
// Weight transpose+convert via smem (64x64 tiles; coalesced reads AND writes)
// z=0..2: Wq/Wk/Wv [H][1024][64] -> gw[z][(h*64+e)][1024]
// z=3:    Wo [1024][1024]        -> gwo[n][1024]
// ===========================================================================
__global__ __launch_bounds__(256)
void conv_wt(const float* __restrict__ Wq, const float* __restrict__ Wk,
             const float* __restrict__ Wv, const float* __restrict__ Wo)
{
    __shared__ uint16_t s[64][66];   // [col][row], pad 66 -> 2-way max
    const int z  = blockIdx.z;
    const int kt = blockIdx.x * 64;
    const int tid = threadIdx.x;

    // load 64 rows x 64 cols fp32, convert, store transposed to smem
#pragma unroll
    for (int i = 0; i < 4; i++) {
        const int idx = i * 256 + tid;
        const int r  = idx >> 4;
        const int c4 = (idx & 15) * 4;
        const float* src;
        if (z < 3) {
            const float* W = (z == 0) ? Wq : (z == 1) ? Wk : Wv;
            src = W + ((size_t)(blockIdx.y * 1024 + kt + r)) * HD + c4;
        } else {
            src = Wo + (size_t)(kt + r) * Dn + blockIdx.y * 64 + c4;
        }
        const float4 w = *(const float4*)src;
        s[c4 + 0][r] = (uint16_t)__half_as_ushort(__float2half_rn(w.x));
        s[c4 + 1][r] = (uint16_t)__half_as_ushort(__float2half_rn(w.y));
        s[c4 + 2][r] = (uint16_t)__half_as_ushort(__float2half_rn(w.z));
        s[c4 + 3][r] = (uint16_t)__half_as_ushort(__float2half_rn(w.w));
    }
    __syncthreads();

    // write out: row = out-col (e or n), 64 k values per row, 32B per thread
    const int e  = tid >> 2;
    const int kq = (tid & 3) * 16;
    uint32_t v32[8];
#pragma unroll
    for (int j = 0; j < 8; j++)
        v32[j] = *(const uint32_t*)&s[e][kq + j * 2];
    hf* dst;
    if (z < 3)
        dst = gw[z] + (size_t)(blockIdx.y * HD + e) * Dn + kt + kq;
    else
        dst = gwo + (size_t)(blockIdx.y * 64 + e) * Dn + kt + kq;
    *(uint4*)(dst)     = *(uint4*)(v32);
    *(uint4*)(dst + 8) = *(uint4*)(v32 + 4);
}

// ===========================================================================
// GEMM (champion, at mma.sync dispatch ceiling): 128x128 CTA tile,
// 256 threads = 8 warps (2m x 4n), warp tile 64x32, K-step 64.
// 3-stage cp.async ring, ONE __syncthreads per K-tile, 2 CTAs/SM.
// Stage: A @0 (16KB), B @16384 (16KB) = 32KB.
// ===========================================================================
#define GSTAGE 32768
#define GEMM_SMEM (3 * GSTAGE)

__device__ __forceinline__ void gemm_stage(uint32_t smb, int buf,
    const hf* Ag, const hf* Bg, int bm, int bn, int kt, int tid)
{
    const uint32_t b0 = smb + buf * GSTAGE;
#pragma unroll
    for (int i = 0; i < 8; i++) {
        const int idx = i * 256 + tid;   // 0..2047
        const int arr = idx >> 10;       // 0=A, 1=B
        const int cidx = idx & 1023;
        const int row = cidx >> 3;       // 0..127
        const int ch  = cidx & 7;        // 16B chunk (0..7)
        const int sub = ch >> 2;
        const int chs = (ch & 3) ^ ((row >> 1) & 3);
        const uint32_t dst = b0 + arr * 16384 + sub * 8192 + row * 64 + chs * 16;
        const hf* g = arr ? (Bg + (size_t)(bn + row) * Dn + kt + ch * 8)
                          : (Ag + (size_t)(bm + row) * Dn + kt + ch * 8);
        CP16(dst, g);
    }
}

__device__ __forceinline__ void gemm_main(uint32_t smb,
    const hf* Ag, const hf* Bg, int bm, int bn, int tid, float c[4][4][4])
{
    const int lane = tid & 31;
    const int warp = tid >> 5;
    const int lrow = lane & 7;
    const int lmat = lane >> 3;
    const int wm = (warp >> 2) * 64;
    const int wn = (warp & 3) * 32;

#pragma unroll
    for (int mi = 0; mi < 4; mi++)
#pragma unroll
        for (int ni = 0; ni < 4; ni++)
#pragma unroll
            for (int r = 0; r < 4; r++) c[mi][ni][r] = 0.f;

    gemm_stage(smb, 0, Ag, Bg, bm, bn, 0, tid);
    CP_COMMIT();
    gemm_stage(smb, 1, Ag, Bg, bm, bn, 64, tid);
    CP_COMMIT();

    const int a_r = (lmat & 1) * 8 + lrow;
    const int b_r = (lmat >> 1) * 8 + lrow;
    const int a_cb = lmat >> 1;
    const int b_cb = lmat & 1;

    int cb = 0, sb = 2;
    const int NT = Dn / 64;   // 16
    for (int t = 0; t < NT; t++) {
        CP_WAIT(1);
        __syncthreads();
        if (t + 2 < NT)
            gemm_stage(smb, sb, Ag, Bg, bm, bn, (t + 2) * 64, tid);
        CP_COMMIT();

        const uint32_t sbase = smb + cb * GSTAGE;
#pragma unroll
        for (int ks = 0; ks < 4; ks++) {
            const uint32_t soff = (uint32_t)((ks >> 1) * 8192);
            const int kk = ks & 1;
            uint32_t ah[4][4];
#pragma unroll
            for (int mi = 0; mi < 4; mi++) {
                const int row = wm + mi * 16 + a_r;
                const int cc = (kk * 2 + a_cb) ^ ((row >> 1) & 3);
                ldmx4(ah[mi], sbase + soff + (uint32_t)(row * 64 + cc * 16));
            }
#pragma unroll
            for (int p = 0; p < 2; p++) {
                const int row = wn + p * 16 + b_r;
                const int cc = (kk * 2 + b_cb) ^ ((row >> 1) & 3);
                uint32_t bh4[4];
                ldmx4(bh4, sbase + 16384 + soff + (uint32_t)(row * 64 + cc * 16));
#pragma unroll
                for (int mi = 0; mi < 4; mi++) {
                    mma_f16(c[mi][2 * p],     ah[mi], bh4);
                    mma_f16(c[mi][2 * p + 1], ah[mi], bh4 + 2);
                }
            }
        }

        cb = (cb == 2) ? 0 : cb + 1;
        sb = (sb == 2) ? 0 : sb + 1;
    }
}

// ---- projection GEMM: z = 0(Q, scaled by 0.125*log2e) / 1(K) / 2(V) ----
__global__ __launch_bounds__(256, 2)
void gemm_proj(const float* __restrict__ bq, const float* __restrict__ bk,
               const float* __restrict__ bv)
{
    extern __shared__ char sm[];
    const uint32_t smb = smem_u32(sm);
    const int tid = threadIdx.x;
    const int z = blockIdx.z;
    const int bm = blockIdx.y * 128;
    const int bn = blockIdx.x * 128;
    const float* bias = (z == 0) ? bq : (z == 1) ? bk : bv;

    float c[4][4][4];
    gemm_main(smb, gx[z], gw[z], bm, bn, tid, c);

    const int lane = tid & 31;
    const int warp = tid >> 5;
    const int g  = lane >> 2;
    const int t2 = (lane & 3) * 2;
    const int wm = (warp >> 2) * 64;
    const int wn = (warp & 3) * 32;
    const float QS = 0.125f * 1.4426950408889634f;   // fold log2(e) into Q

#pragma unroll
    for (int mi = 0; mi < 4; mi++) {
        const int row0 = bm + wm + mi * 16 + g;
        const int b  = row0 >> 11;
        const int s0 = row0 & (Sn - 1);
#pragma unroll
        for (int ni = 0; ni < 4; ni++) {
            const int col = bn + wn + ni * 8 + t2;
            const int h = col >> 6, e = col & 63;
            float v00 = c[mi][ni][0] + bias[col];
            float v01 = c[mi][ni][1] + bias[col + 1];
            float v10 = c[mi][ni][2] + bias[col];
            float v11 = c[mi][ni][3] + bias[col + 1];
            if (z == 0) { v00 *= QS; v01 *= QS; v10 *= QS; v11 *= QS; }
            const size_t r0 = ((size_t)(b * Hn + h) * Sn + s0) * HD + e;
            hf* D = (z == 0) ? gQ : (z == 1) ? gK : gV;
            *(uint32_t*)(D + r0)          = pack_f16(v00, v01);
            *(uint32_t*)(D + r0 + 8 * HD) = pack_f16(v10, v11);
        }
    }
}

// ---- final GEMM: cat @ Wo + bo -> out (f32) ----
__global__ __launch_bounds__(256, 2)
void gemm_out(const float* __restrict__ bo, float* __restrict__ out)
{
    extern __shared__ char sm[];
    const uint32_t smb = smem_u32(sm);
    const int tid = threadIdx.x;
    const int bm = blockIdx.y * 128;
    const int bn = blockIdx.x * 128;

    float c[4][4][4];
    gemm_main(smb, gC, gwo, bm, bn, tid, c);

    const int lane = tid & 31;
    const int warp = tid >> 5;
    const int g  = lane >> 2;
    const int t2 = (lane & 3) * 2;
    const int wm = (warp >> 2) * 64;
    const int wn = (warp & 3) * 32;

#pragma unroll
    for (int mi = 0; mi < 4; mi++) {
        const int row0 = bm + wm + mi * 16 + g;
#pragma unroll
        for (int ni = 0; ni < 4; ni++) {
            const int col = bn + wn + ni * 8 + t2;
            const float b0v = bo[col], b1v = bo[col + 1];
            *(float2*)(out + (size_t)row0 * Dn + col) =
                make_float2(c[mi][ni][0] + b0v, c[mi][ni][1] + b1v);
            *(float2*)(out + (size_t)(row0 + 8) * Dn + col) =
                make_float2(c[mi][ni][2] + b0v, c[mi][ni][3] + b1v);
        }
    }
}

// ===========================================================================
// Flash attention. 256 q-rows per CTA, 512 threads (16 warps), each warp
// owns 16 q-rows. K-tile 128 as two 64-key sub-tiles, 3-stage ring.
// V stored ROW-MAJOR [s][64]; PV B-fragments via ldmatrix.x4.trans.
// Stage: K[128x64] pad 144B/row @0 (18432B), V[128x64] same @18432.
// Stride 36864.
// ===========================================================================
#define AST 36864
#define ATTN_SMEM (3 * AST)

__device__ __forceinline__ void attn_stage(uint32_t smb, int buf, int bh,
                                           int kt, int tid)
{
    const uint32_t b0 = smb + buf * AST;
#pragma unroll
    for (int i = 0; i < 4; i++) {
        const int idx = i * 512 + tid;      // 0..2047
        const int arr = idx >> 10;          // 0=K, 1=V
        const int cidx = idx & 1023;
        const int row = cidx >> 3;          // 0..127
        const int ch  = cidx & 7;
        const uint32_t dst = b0 + arr * 18432 + row * 144 + ch * 16;
        const hf* g = (arr ? gV : gK) + ((size_t)bh * Sn + kt + row) * HD + ch * 8;
        CP16(dst, g);
    }
}

__global__ __launch_bounds__(512, 1)
void attn_mma()
{
    extern __shared__ char sm[];
    const uint32_t smb = smem_u32(sm);
    const int tid  = threadIdx.x;
    const int lane = tid & 31;
    const int warp = tid >> 5;           // 0..15
    const int g  = lane >> 2;
    const int t2 = (lane & 3) * 2;
    const int lrow = lane & 7;
    const int lmat = lane >> 3;
    const int bh = blockIdx.y;
    const int q0 = blockIdx.x * 256;
    const int mr = warp * 16;            // warp's 16 q-rows

    // ---- Q fragments ----
    uint32_t qh[4][4];
    {
        const hf* h0 = gQ + ((size_t)bh * Sn + q0 + mr + g) * HD;
        const hf* h1 = h0 + 8 * HD;
#pragma unroll
        for (int ks = 0; ks < 4; ks++) {
            const int kc = ks * 16 + t2;
            qh[ks][0] = *(const uint32_t*)(h0 + kc);
            qh[ks][1] = *(const uint32_t*)(h1 + kc);
            qh[ks][2] = *(const uint32_t*)(h0 + kc + 8);
            qh[ks][3] = *(const uint32_t*)(h1 + kc + 8);
        }
    }

    float O[8][4];
#pragma unroll
    for (int ef = 0; ef < 8; ef++)
#pragma unroll
        for (int r = 0; r < 4; r++) O[ef][r] = 0.f;
    float rsum[4] = {0.f, 0.f, 0.f, 0.f};
    const uint32_t ones2[2] = {0x3C003C00u, 0x3C003C00u};

    attn_stage(smb, 0, bh, 0, tid);
    CP_COMMIT();
    attn_stage(smb, 1, bh, 128, tid);
    CP_COMMIT();

    const uint32_t krow_off  = (uint32_t)(((lmat >> 1) * 8 + lrow) * 144);
    // trans V: lane addresses source row s = (lmat&1)*8+lrow, col e-block = lmat>>1
    const uint32_t vtrow_off = (uint32_t)(((lmat & 1) * 8 + lrow) * 144);
    const uint32_t vcol_off  = (uint32_t)((lmat >> 1) * 16);

    int cb = 0;
    int sb = 2;
    const int NT = Sn / 128;   // 16
    for (int t = 0; t < NT; t++) {
        CP_WAIT(1);
        __syncthreads();
        if (t + 2 < NT) attn_stage(smb, sb, bh, (t + 2) * 128, tid);
        CP_COMMIT();

        const uint32_t kbase = smb + cb * AST;
        const uint32_t vbase = kbase + 18432;

#pragma unroll
        for (int u = 0; u < 2; u++) {        // two 64-key sub-tiles
            const uint32_t ksub = kbase + (uint32_t)(u * 9216);

            // ---- S = Q K^T (64 key cols) ----
            float sc[8][4];
#pragma unroll
            for (int nf = 0; nf < 8; nf++)
#pragma unroll
                for (int r = 0; r < 4; r++) sc[nf][r] = 0.f;

#pragma unroll
            for (int ks = 0; ks < 4; ks++) {
                const uint32_t kcol = (uint32_t)((ks * 16 + (lmat & 1) * 8) * 2);
#pragma unroll
                for (int p = 0; p < 4; p++) {
                    const uint32_t ka = ksub + (uint32_t)(p * 2304) + krow_off + kcol;
                    uint32_t kh4[4];
                    ldmx4(kh4, ka);
                    mma_f16(sc[2 * p],     qh[ks], kh4);
                    mma_f16(sc[2 * p + 1], qh[ks], kh4 + 2);
                }
            }

            // ---- softmax chunk + PV chunk interleaved ----
#pragma unroll
            for (int ks2 = 0; ks2 < 4; ks2++) {
                uint32_t ph[4];
                ph[0] = ex2_h2(pack_f16(sc[2 * ks2][0],     sc[2 * ks2][1]));
                ph[1] = ex2_h2(pack_f16(sc[2 * ks2][2],     sc[2 * ks2][3]));
                ph[2] = ex2_h2(pack_f16(sc[2 * ks2 + 1][0], sc[2 * ks2 + 1][1]));
                ph[3] = ex2_h2(pack_f16(sc[2 * ks2 + 1][2], sc[2 * ks2 + 1][3]));
                mma_f16(rsum, ph, ones2);
                // V rows s = (u*64 + ks2*16) .. +15, cols e = p*16 .. +15
                const uint32_t vs = vbase
                    + (uint32_t)((u * 64 + ks2 * 16) * 144)
                    + vtrow_off + vcol_off;
#pragma unroll
                for (int p = 0; p < 4; p++) {
                    uint32_t vh4[4];
                    ldmx4t(vh4, vs + (uint32_t)(p * 32));
                    mma_f16(O[2 * p],     ph, vh4);
                    mma_f16(O[2 * p + 1], ph, vh4 + 2);
                }
            }
        }

        cb = (cb == 2) ? 0 : cb + 1;
        sb = (sb == 2) ? 0 : sb + 1;
    }

    // ---- normalize + write fp16 concat ----
    const int b = bh >> 4;
    const int h = bh & 15;
    const float i0 = 1.f / rsum[0];
    const float i1 = 1.f / rsum[2];
    const int s0 = q0 + mr + g;
    const size_t base0 = (size_t)(b * Sn + s0) * Dn + h * HD;
    const size_t base1 = (size_t)(b * Sn + s0 + 8) * Dn + h * HD;
#pragma unroll
    for (int ef = 0; ef < 8; ef++) {
        const int e = ef * 8 + t2;
        *(uint32_t*)(gC + base0 + e) = pack_f16(O[ef][0] * i0, O[ef][1] * i0);
        *(uint32_t*)(gC + base1 + e) = pack_f16(O[ef][2] * i1, O[ef][3] * i1);
    }
}

// ---------------------------------------------------------------------------
extern "C" void kernel_launch(void* const* d_in, const int* in_sizes, int n_in,
                              void* d_out, int out_size)
{
    const float* q  = (const float*)d_in[0];
    const float* k  = (const float*)d_in[1];
    const float* v  = (const float*)d_in[2];
    const float* Wq = (const float*)d_in[3];
    const float* bq = (const float*)d_in[4];
    const float* Wk = (const float*)d_in[5];
    const float* bk = (const float*)d_in[6];
    const float* Wv = (const float*)d_in[7];
    const float* bv = (const float*)d_in[8];
    const float* Wo = (const float*)d_in[9];
    const float* bo = (const float*)d_in[10];
    float* out = (float*)d_out;

    cudaFuncSetAttribute(gemm_proj,
                         cudaFuncAttributeMaxDynamicSharedMemorySize, GEMM_SMEM);
    cudaFuncSetAttribute(gemm_out,
                         cudaFuncAttributeMaxDynamicSharedMemorySize, GEMM_SMEM);
    cudaFuncSetAttribute(attn_mma,
                         cudaFuncAttributeMaxDynamicSharedMemorySize, ATTN_SMEM);

    // 1) one-time conversions (inputs coalesced; weights via smem transpose)
    conv_in<<<dim3(MK / 8 / 256, 1, 3), 256>>>(q, k, v);
    conv_wt<<<dim3(16, 16, 4), 256>>>(Wq, Wk, Wv, Wo);

    // 2) fused Q/K/V projections (grid.z selects head path)
    gemm_proj<<<dim3(8, 32, 3), 256, GEMM_SMEM>>>(bq, bk, bv);

    // 3) attention (256 q-rows per CTA, 512 threads)
    attn_mma<<<dim3(Sn / 256, Bn * Hn), 512, ATTN_SMEM>>>();

    // 4) output projection
    gemm_out<<<dim3(8, 32), 256, GEMM_SMEM>>>(bo, out);
}